// round 8
// baseline (speedup 1.0000x reference)
#include <cuda_runtime.h>
#include <cuda_fp16.h>
#include <cstdint>

#define BATCH 8
#define SEQ   2048
#define CDIM  1024
#define HDIM  64

// ---------------- persistent scratch ----------------
__device__ __half g_wth[3 * HDIM * CDIM];          // [192 n][1024 k] fp16 W^T
__device__ __half g_qh[BATCH * SEQ * HDIM];
__device__ __half g_kh[BATCH * SEQ * HDIM];
__device__ __half g_vh[BATCH * SEQ * HDIM];
__device__ float  g_partO[4][BATCH * SEQ * HDIM];
__device__ float  g_partL[4][BATCH * SEQ];

// ---------------- helpers ----------------
__device__ __forceinline__ uint32_t smem_u32(const void* p) {
    uint32_t a;
    asm("{ .reg .u64 t; cvta.to.shared.u64 t, %1; cvt.u32.u64 %0, t; }" : "=r"(a) : "l"(p));
    return a;
}
__device__ __forceinline__ void cp16(uint32_t dst, const void* src) {
    asm volatile("cp.async.cg.shared.global [%0], [%1], 16;" :: "r"(dst), "l"(src));
}
#define CP_COMMIT asm volatile("cp.async.commit_group;" ::: "memory")
#define CP_WAIT0  asm volatile("cp.async.wait_group 0;" ::: "memory")
#define CP_WAIT1  asm volatile("cp.async.wait_group 1;" ::: "memory")

// pack two f32 -> f16x2 (lo = first arg)
__device__ __forceinline__ uint32_t packh2(float lo, float hi) {
    uint32_t d;
    asm("cvt.rn.f16x2.f32 %0, %1, %2;" : "=r"(d) : "f"(hi), "f"(lo));
    return d;
}

// D(16x8,f32) += A(16x16,f16,row) * B(16x8,f16,col)
__device__ __forceinline__ void mma16(float* c, const uint32_t* a, uint32_t b0, uint32_t b1) {
    asm volatile(
        "mma.sync.aligned.m16n8k16.row.col.f32.f16.f16.f32 "
        "{%0,%1,%2,%3}, {%4,%5,%6,%7}, {%8,%9}, {%0,%1,%2,%3};"
        : "+f"(c[0]), "+f"(c[1]), "+f"(c[2]), "+f"(c[3])
        : "r"(a[0]), "r"(a[1]), "r"(a[2]), "r"(a[3]), "r"(b0), "r"(b1));
}

// ================= Kernel 0: W transpose + fp16 =================
__global__ void wt_kernel(const float* __restrict__ Wq,
                          const float* __restrict__ Wk,
                          const float* __restrict__ Wv)
{
    const float* W = (blockIdx.z == 0) ? Wq : (blockIdx.z == 1) ? Wk : Wv;
    __shared__ float tile[32][33];
    int c0 = blockIdx.x * 32, h0 = blockIdx.y * 32;
    tile[threadIdx.y][threadIdx.x] = W[(size_t)(c0 + threadIdx.y) * HDIM + h0 + threadIdx.x];
    __syncthreads();
    g_wth[(size_t)blockIdx.z * HDIM * CDIM + (size_t)(h0 + threadIdx.y) * CDIM + c0 + threadIdx.x] =
        __float2half_rn(tile[threadIdx.x][threadIdx.y]);
}

// ================= Kernel 1: fused QKV projection (fp16 mma) =================
// grid 256: 64-row M-tile. K-chunk 32, double-buffered.
// SMEM words: A0[64*20]@0  A1@1280  B0[192*20]@2560  B1@6400  -> 40960 B
#define QKV_SMEM_BYTES 40960

__global__ void __launch_bounds__(256, 2) qkv_mma(const float* __restrict__ x)
{
    extern __shared__ uint32_t smw[];
    const uint32_t sb = smem_u32(smw);
    const int t = threadIdx.x, lane = t & 31, warp = t >> 5;
    const int g = lane >> 2, t4 = lane & 3;
    const int wm = warp >> 2, wn = warp & 3;          // 2M x 4N warp layout
    const int Mbase = blockIdx.x * 64;

    float acc[2][6][4];
#pragma unroll
    for (int a = 0; a < 2; a++)
#pragma unroll
        for (int b = 0; b < 6; b++)
#pragma unroll
            for (int c = 0; c < 4; c++) acc[a][b][c] = 0.0f;

    const int xr = t >> 2, xj = t & 3;                // A-fill task: row, 8-col group

    auto ldgX = [&](int c, float4* v) {
        const float* src = x + (size_t)(Mbase + xr) * CDIM + c * 32 + xj * 8;
        v[0] = *reinterpret_cast<const float4*>(src);
        v[1] = *reinterpret_cast<const float4*>(src + 4);
    };
    auto stsX = [&](int st, const float4* v) {
        uint4 h;
        h.x = packh2(v[0].x, v[0].y); h.y = packh2(v[0].z, v[0].w);
        h.z = packh2(v[1].x, v[1].y); h.w = packh2(v[1].z, v[1].w);
        *reinterpret_cast<uint4*>(smw + st * 1280 + xr * 20 + xj * 4) = h;
    };
    auto issueB = [&](int c, int st) {
        uint32_t bb = sb + (2560u + (uint32_t)st * 3840u) * 4u;
#pragma unroll
        for (int i = 0; i < 3; i++) {                  // 192 rows x 32 halves
            int idx = t + i * 256;
            int n = idx >> 2, j = idx & 3;
            cp16(bb + (uint32_t)(n * 20 + j * 4) * 4u,
                 g_wth + (size_t)n * CDIM + c * 32 + j * 8);
        }
    };

    float4 xa[2];
    ldgX(0, xa); stsX(0, xa);
    issueB(0, 0); CP_COMMIT;

    for (int c = 0; c < 32; c++) {
        const int st = c & 1;
        if (c < 31) { issueB(c + 1, st ^ 1); CP_COMMIT; CP_WAIT1; ldgX(c + 1, xa); }
        else        { CP_WAIT0; }
        __syncthreads();

        const uint32_t* As = smw + st * 1280;
        const uint32_t* Bs = smw + 2560 + st * 3840;

#pragma unroll
        for (int kk = 0; kk < 2; kk++) {               // two k16 steps per 32-chunk
            uint32_t af[2][4];
#pragma unroll
            for (int mt = 0; mt < 2; mt++) {
                int r = wm * 32 + mt * 16;
                af[mt][0] = As[(r + g)     * 20 + kk * 8 + t4];
                af[mt][1] = As[(r + g + 8) * 20 + kk * 8 + t4];
                af[mt][2] = As[(r + g)     * 20 + kk * 8 + t4 + 4];
                af[mt][3] = As[(r + g + 8) * 20 + kk * 8 + t4 + 4];
            }
#pragma unroll
            for (int nt = 0; nt < 6; nt++) {
                int n = wn * 48 + nt * 8 + g;
                uint32_t b0 = Bs[n * 20 + kk * 8 + t4];
                uint32_t b1 = Bs[n * 20 + kk * 8 + t4 + 4];
                mma16(acc[0][nt], af[0], b0, b1);
                mma16(acc[1][nt], af[1], b0, b1);
            }
        }
        __syncthreads();                               // stage st reads done
        if (c < 31) stsX(st ^ 1, xa);                  // A for c+1 into other stage
    }

    // epilogue: fp16 q/k/v
#pragma unroll
    for (int mt = 0; mt < 2; mt++) {
        int r0 = Mbase + wm * 32 + mt * 16 + g;
#pragma unroll
        for (int nt = 0; nt < 6; nt++) {
            int ncol = wn * 48 + nt * 8 + 2 * t4;
            int w = ncol >> 6, cc = ncol & 63;
            __half* outp = (w == 0) ? g_qh : (w == 1) ? g_kh : g_vh;
            *reinterpret_cast<uint32_t*>(outp + (size_t)r0 * HDIM + cc) =
                packh2(acc[mt][nt][0], acc[mt][nt][1]);
            *reinterpret_cast<uint32_t*>(outp + (size_t)(r0 + 8) * HDIM + cc) =
                packh2(acc[mt][nt][2], acc[mt][nt][3]);
        }
    }
}

// ================= Kernel 2: split-K causal attention (fp16 mma) =================
// 320 CTAs, max 4 key-tile iters each, heavy splits first.
// SMEM words: K0[128*36]@0  K1@4608  VT[64*68]@9216  P/Q[128*36]@13568 -> 72704 B
#define ATTN_SMEM_BYTES 72704

__global__ void __launch_bounds__(256, 2) attn_split()
{
    extern __shared__ uint32_t smw[];
    const uint32_t sb = smem_u32(smw);
    const int t = threadIdx.x, lane = t & 31, warp = t >> 5;
    const int g = lane >> 2, t4 = lane & 3;

    const int bid = blockIdx.x;
    const int b = bid / 40, r = bid % 40;
    int qt, s, ns;
    if (r < 16)      { qt = 12 + (r >> 2);      s = r & 3;        ns = 4; }
    else if (r < 28) { qt = 8 + (r - 16) / 3;   s = (r - 16) % 3; ns = 3; }
    else if (r < 36) { qt = 4 + (r - 28) / 2;   s = (r - 28) % 2; ns = 2; }
    else             { qt = r - 36;             s = 0;            ns = 1; }
    const int len = qt + 1;
    const int k0t = s * len / ns, k1t = (s + 1) * len / ns;
    const int qBase = qt * 128;

    const __half* kg = g_kh + (size_t)b * SEQ * HDIM;
    const __half* vg = g_vh + (size_t)b * SEQ * HDIM;

    auto issueK = [&](int kt, int st) {
        uint32_t kb = sb + (uint32_t)st * 4608u * 4u;
#pragma unroll
        for (int i = 0; i < 4; i++) {
            int idx = t + i * 256;
            int rr = idx >> 3, j = idx & 7;
            cp16(kb + (uint32_t)(rr * 36 + j * 4) * 4u,
                 kg + (size_t)(kt * 128 + rr) * HDIM + j * 8);
        }
    };
    const int vp = t & 63, vq = t >> 6;                 // key-pair, 8-half group base
    auto ldgV = [&](int kt, uint4* vr) {
#pragma unroll
        for (int it = 0; it < 2; it++) {
            int p = vp, q8 = vq + it * 4;
            const __half* src = vg + (size_t)(kt * 128 + 2 * p) * HDIM + q8 * 8;
            vr[it * 2]     = *reinterpret_cast<const uint4*>(src);
            vr[it * 2 + 1] = *reinterpret_cast<const uint4*>(src + HDIM);
        }
    };
    auto stsV = [&](const uint4* vr) {
#pragma unroll
        for (int it = 0; it < 2; it++) {
            int p = vp, q8 = vq + it * 4;
            const uint16_t* r0h = reinterpret_cast<const uint16_t*>(&vr[it * 2]);
            const uint16_t* r1h = reinterpret_cast<const uint16_t*>(&vr[it * 2 + 1]);
#pragma unroll
            for (int i = 0; i < 8; i++) {
                smw[9216 + (q8 * 8 + i) * 68 + p] =
                    (uint32_t)r0h[i] | ((uint32_t)r1h[i] << 16);
            }
        }
    };

    // prologue: K(k0t) + Q via cp.async; V(k0t) via regs
    issueK(k0t, 0);
    {
        const __half* qg = g_qh + ((size_t)b * SEQ + qBase) * HDIM;
#pragma unroll
        for (int i = 0; i < 4; i++) {
            int idx = t + i * 256;
            int rr = idx >> 3, j = idx & 7;
            cp16(sb + (uint32_t)(13568 + rr * 36 + j * 4) * 4u,
                 qg + (size_t)rr * HDIM + j * 8);
        }
    }
    CP_COMMIT;
    uint4 vr[4];
    ldgV(k0t, vr);
    CP_WAIT0;
    __syncthreads();

    uint32_t qf[4][4];
    {
        const uint32_t* Qs = smw + 13568;
        int r0 = warp * 16;
#pragma unroll
        for (int kk = 0; kk < 4; kk++) {
            qf[kk][0] = Qs[(r0 + g)     * 36 + kk * 8 + t4];
            qf[kk][1] = Qs[(r0 + g + 8) * 36 + kk * 8 + t4];
            qf[kk][2] = Qs[(r0 + g)     * 36 + kk * 8 + t4 + 4];
            qf[kk][3] = Qs[(r0 + g + 8) * 36 + kk * 8 + t4 + 4];
        }
    }
    stsV(vr);
    __syncthreads();                                   // qf reads done, V^T visible

    float oacc[8][4];
#pragma unroll
    for (int a = 0; a < 8; a++)
#pragma unroll
        for (int c = 0; c < 4; c++) oacc[a][c] = 0.0f;
    float rs0 = 0.0f, rs1 = 0.0f;
    const int r0l = warp * 16 + g;
    uint32_t* Ps = smw + 13568;                        // stride 36 words (64-wide P)

    for (int kt = k0t; kt < k1t; kt++) {
        const int st = (kt - k0t) & 1;
        const bool more = (kt + 1 < k1t);
        if (more) { issueK(kt + 1, st ^ 1); CP_COMMIT; ldgV(kt + 1, vr); }
        const uint32_t* Ks = smw + st * 4608;
        const bool dtile = (kt == qt);

#pragma unroll
        for (int hl = 0; hl < 2; hl++) {
            // ---- S half: 128q x 64 keys ----
            float sacc[8][4];
#pragma unroll
            for (int a = 0; a < 8; a++)
#pragma unroll
                for (int c = 0; c < 4; c++) sacc[a][c] = 0.0f;
#pragma unroll
            for (int nt = 0; nt < 8; nt++) {
                const int key = hl * 64 + nt * 8 + g;
#pragma unroll
                for (int kk = 0; kk < 4; kk++) {
                    uint32_t b0 = Ks[key * 36 + kk * 8 + t4];
                    uint32_t b1 = Ks[key * 36 + kk * 8 + t4 + 4];
                    mma16(sacc[nt], qf[kk], b0, b1);
                }
            }
            // ---- exp + mask + rowsum + P(fp16) ----
#pragma unroll
            for (int nt = 0; nt < 8; nt++) {
                int c0 = hl * 64 + nt * 8 + 2 * t4;
                float p00 = __expf(sacc[nt][0] * 0.125f);
                float p01 = __expf(sacc[nt][1] * 0.125f);
                float p10 = __expf(sacc[nt][2] * 0.125f);
                float p11 = __expf(sacc[nt][3] * 0.125f);
                if (dtile) {
                    if (c0     > r0l)     p00 = 0.0f;
                    if (c0 + 1 > r0l)     p01 = 0.0f;
                    if (c0     > r0l + 8) p10 = 0.0f;
                    if (c0 + 1 > r0l + 8) p11 = 0.0f;
                }
                rs0 += p00 + p01;
                rs1 += p10 + p11;
                Ps[r0l * 36       + nt * 4 + t4] = packh2(p00, p01);
                Ps[(r0l + 8) * 36 + nt * 4 + t4] = packh2(p10, p11);
            }
            __syncwarp();
            // ---- O += P_half @ V^T half ----
#pragma unroll
            for (int kk = 0; kk < 4; kk++) {
                uint32_t af[4];
                af[0] = Ps[(warp * 16 + g)     * 36 + kk * 8 + t4];
                af[1] = Ps[(warp * 16 + g + 8) * 36 + kk * 8 + t4];
                af[2] = Ps[(warp * 16 + g)     * 36 + kk * 8 + t4 + 4];
                af[3] = Ps[(warp * 16 + g + 8) * 36 + kk * 8 + t4 + 4];
#pragma unroll
                for (int nt = 0; nt < 8; nt++) {
                    uint32_t b0 = smw[9216 + (nt * 8 + g) * 68 + hl * 32 + kk * 8 + t4];
                    uint32_t b1 = smw[9216 + (nt * 8 + g) * 68 + hl * 32 + kk * 8 + t4 + 4];
                    mma16(oacc[nt], af, b0, b1);
                }
            }
            __syncwarp();
        }
        __syncthreads();                               // V^T/P reads done CTA-wide
        if (more) { stsV(vr); CP_WAIT0; }
        __syncthreads();                               // next K + V^T visible
    }

    // ---- partial epilogue ----
    rs0 += __shfl_xor_sync(0xffffffffu, rs0, 1);
    rs0 += __shfl_xor_sync(0xffffffffu, rs0, 2);
    rs1 += __shfl_xor_sync(0xffffffffu, rs1, 1);
    rs1 += __shfl_xor_sync(0xffffffffu, rs1, 2);

    float* po = g_partO[s] + ((size_t)b * SEQ + qBase + r0l) * HDIM;
#pragma unroll
    for (int nt = 0; nt < 8; nt++) {
        int cc = nt * 8 + 2 * t4;
        float2 v0 = { oacc[nt][0], oacc[nt][1] };
        *reinterpret_cast<float2*>(po + cc) = v0;
        float2 v1 = { oacc[nt][2], oacc[nt][3] };
        *reinterpret_cast<float2*>(po + (size_t)8 * HDIM + cc) = v1;
    }
    if (t4 == 0) {
        g_partL[s][(size_t)b * SEQ + qBase + r0l]     = rs0;
        g_partL[s][(size_t)b * SEQ + qBase + r0l + 8] = rs1;
    }
}

// ================= Kernel 3: combine splits + normalize =================
__global__ void __launch_bounds__(256) combine_kernel(float* __restrict__ out)
{
    int gid = blockIdx.x * 256 + threadIdx.x;          // one float4 per thread
    int row = gid >> 4;
    int qt = (row & (SEQ - 1)) >> 7;
    int ns = (qt + 4) / 4;

    float4 o = reinterpret_cast<const float4*>(g_partO[0])[gid];
    float  l = g_partL[0][row];
#pragma unroll
    for (int s = 1; s < 4; s++) {
        if (ns > s) {
            float4 os = reinterpret_cast<const float4*>(g_partO[s])[gid];
            o.x += os.x; o.y += os.y; o.z += os.z; o.w += os.w;
            l += g_partL[s][row];
        }
    }
    float inv = 1.0f / l;
    o.x *= inv; o.y *= inv; o.z *= inv; o.w *= inv;
    reinterpret_cast<float4*>(out)[gid] = o;
}

// ---------------- launch ----------------
extern "C" void kernel_launch(void* const* d_in, const int* in_sizes, int n_in,
                              void* d_out, int out_size)
{
    const float* x  = (const float*)d_in[0];
    const float* Wq = (const float*)d_in[1];
    const float* Wk = (const float*)d_in[2];
    const float* Wv = (const float*)d_in[3];
    float* out = (float*)d_out;

    wt_kernel<<<dim3(CDIM / 32, HDIM / 32, 3), dim3(32, 32)>>>(Wq, Wk, Wv);

    cudaFuncSetAttribute(qkv_mma, cudaFuncAttributeMaxDynamicSharedMemorySize,
                         QKV_SMEM_BYTES);
    qkv_mma<<<(BATCH * SEQ) / 64, 256, QKV_SMEM_BYTES>>>(x);

    cudaFuncSetAttribute(attn_split, cudaFuncAttributeMaxDynamicSharedMemorySize,
                         ATTN_SMEM_BYTES);
    attn_split<<<320, 256, ATTN_SMEM_BYTES>>>();

    combine_kernel<<<(BATCH * SEQ * HDIM / 4) / 256, 256>>>(out);
}

// round 11
// speedup vs baseline: 1.7066x; 1.7066x over previous
#include <cuda_runtime.h>
#include <cuda_fp16.h>
#include <cstdint>

#define BATCH 8
#define SEQ   2048
#define CDIM  1024
#define HDIM  64

// ---------------- persistent scratch ----------------
__device__ __half g_wth[3 * HDIM * CDIM];          // [192 n][1024 k] fp16 W^T
__device__ __half g_qh[BATCH * SEQ * HDIM];
__device__ __half g_kh[BATCH * SEQ * HDIM];
__device__ __half g_vh[BATCH * SEQ * HDIM];
__device__ float  g_partO[4][BATCH * SEQ * HDIM];
__device__ float  g_partL[4][BATCH * SEQ];

// ---------------- helpers ----------------
__device__ __forceinline__ uint32_t smem_u32(const void* p) {
    uint32_t a;
    asm("{ .reg .u64 t; cvta.to.shared.u64 t, %1; cvt.u32.u64 %0, t; }" : "=r"(a) : "l"(p));
    return a;
}
__device__ __forceinline__ void cp16(uint32_t dst, const void* src) {
    asm volatile("cp.async.cg.shared.global [%0], [%1], 16;" :: "r"(dst), "l"(src));
}
#define CP_COMMIT asm volatile("cp.async.commit_group;" ::: "memory")
#define CP_WAIT0  asm volatile("cp.async.wait_group 0;" ::: "memory")

__device__ __forceinline__ uint32_t packh2(float lo, float hi) {
    uint32_t d;
    asm("cvt.rn.f16x2.f32 %0, %1, %2;" : "=r"(d) : "f"(hi), "f"(lo));
    return d;
}
__device__ __forceinline__ void mma16(float* c, const uint32_t* a, uint32_t b0, uint32_t b1) {
    asm volatile(
        "mma.sync.aligned.m16n8k16.row.col.f32.f16.f16.f32 "
        "{%0,%1,%2,%3}, {%4,%5,%6,%7}, {%8,%9}, {%0,%1,%2,%3};"
        : "+f"(c[0]), "+f"(c[1]), "+f"(c[2]), "+f"(c[3])
        : "r"(a[0]), "r"(a[1]), "r"(a[2]), "r"(a[3]), "r"(b0), "r"(b1));
}
__device__ __forceinline__ void ldm4(uint32_t* r, uint32_t addr) {
    asm volatile("ldmatrix.sync.aligned.m8n8.x4.shared.b16 {%0,%1,%2,%3}, [%4];"
                 : "=r"(r[0]), "=r"(r[1]), "=r"(r[2]), "=r"(r[3]) : "r"(addr));
}

// ================= Kernel 0: W transpose + fp16 =================
__global__ void wt_kernel(const float* __restrict__ Wq,
                          const float* __restrict__ Wk,
                          const float* __restrict__ Wv)
{
    const float* W = (blockIdx.z == 0) ? Wq : (blockIdx.z == 1) ? Wk : Wv;
    __shared__ float tile[32][33];
    int c0 = blockIdx.x * 32, h0 = blockIdx.y * 32;
    tile[threadIdx.y][threadIdx.x] = W[(size_t)(c0 + threadIdx.y) * HDIM + h0 + threadIdx.x];
    __syncthreads();
    g_wth[(size_t)blockIdx.z * HDIM * CDIM + (size_t)(h0 + threadIdx.y) * CDIM + c0 + threadIdx.x] =
        __float2half_rn(tile[threadIdx.x][threadIdx.y]);
}

// ================= Kernel 1: fused QKV projection =================
// grid 256: 64-row M-tile. K-chunk 64 (4 k16 steps), double-buffered, 1 sync/iter.
// SMEM words: A0[64*36]@0  A1@2304  B0[192*36]@4608  B1@11520  -> 73728 B
#define QKV_SMEM_BYTES 73728

__global__ void __launch_bounds__(256, 2) qkv_mma(const float* __restrict__ x)
{
    extern __shared__ uint32_t smw[];
    const uint32_t sb = smem_u32(smw);
    const int t = threadIdx.x, lane = t & 31, warp = t >> 5;
    const int g = lane >> 2, t4 = lane & 3;
    const int wm = warp >> 2, wn = warp & 3;           // 2M x 4N warps
    const int Mbase = blockIdx.x * 64;

    // ldmatrix lane offsets
    const uint32_t arow = lane & 15;                   // A: 16-row tiles
    const uint32_t asel = (uint32_t)((lane >> 4) << 4);
    const uint32_t nrow = (uint32_t)(((lane >> 4) << 3) + (lane & 7));  // B: 8-row pairs
    const uint32_t bsel = (uint32_t)(((lane >> 3) & 1) << 4);

    float acc[2][6][4];
#pragma unroll
    for (int a = 0; a < 2; a++)
#pragma unroll
        for (int b = 0; b < 6; b++)
#pragma unroll
            for (int c = 0; c < 4; c++) acc[a][b][c] = 0.0f;

    const int xr = t >> 2, xj = t & 3;                 // A fill: row, 16-col group

    auto ldgX = [&](int c, float4* v) {
        const float* src = x + (size_t)(Mbase + xr) * CDIM + c * 64 + xj * 16;
#pragma unroll
        for (int i = 0; i < 4; i++) v[i] = *reinterpret_cast<const float4*>(src + i * 4);
    };
    auto stsX = [&](int st, const float4* v) {
        uint4 h0, h1;
        h0.x = packh2(v[0].x, v[0].y); h0.y = packh2(v[0].z, v[0].w);
        h0.z = packh2(v[1].x, v[1].y); h0.w = packh2(v[1].z, v[1].w);
        h1.x = packh2(v[2].x, v[2].y); h1.y = packh2(v[2].z, v[2].w);
        h1.z = packh2(v[3].x, v[3].y); h1.w = packh2(v[3].z, v[3].w);
        *reinterpret_cast<uint4*>(smw + st * 2304 + xr * 36 + xj * 8)     = h0;
        *reinterpret_cast<uint4*>(smw + st * 2304 + xr * 36 + xj * 8 + 4) = h1;
    };
    auto issueB = [&](int c, int st) {
        uint32_t bb = sb + (4608u + (uint32_t)st * 6912u) * 4u;
#pragma unroll
        for (int i = 0; i < 6; i++) {                  // 192 rows x 64 halves
            int idx = t + i * 256;
            int n = idx >> 3, j = idx & 7;
            cp16(bb + (uint32_t)(n * 36 + j * 4) * 4u,
                 g_wth + (size_t)n * CDIM + c * 64 + j * 8);
        }
    };

    float4 xa[4];
    ldgX(0, xa); stsX(0, xa);
    issueB(0, 0); CP_COMMIT;

    for (int c = 0; c < 16; c++) {
        const int st = c & 1;
        CP_WAIT0;
        __syncthreads();                               // B(st), A(st) visible; prev readers done
        if (c < 15) { issueB(c + 1, st ^ 1); CP_COMMIT; ldgX(c + 1, xa); }

        const uint32_t Ab = sb + (uint32_t)st * 2304u * 4u;
        const uint32_t Bb = sb + (4608u + (uint32_t)st * 6912u) * 4u;

#pragma unroll
        for (int kk = 0; kk < 4; kk++) {
            uint32_t af0[4], af1[4];
            ldm4(af0, Ab + (wm * 32 +      arow) * 144u + kk * 32u + asel);
            ldm4(af1, Ab + (wm * 32 + 16 + arow) * 144u + kk * 32u + asel);
#pragma unroll
            for (int j = 0; j < 3; j++) {
                uint32_t bf[4];
                ldm4(bf, Bb + (wn * 48 + j * 16 + nrow) * 144u + kk * 32u + bsel);
                mma16(acc[0][2 * j],     af0, bf[0], bf[1]);
                mma16(acc[0][2 * j + 1], af0, bf[2], bf[3]);
                mma16(acc[1][2 * j],     af1, bf[0], bf[1]);
                mma16(acc[1][2 * j + 1], af1, bf[2], bf[3]);
            }
        }
        if (c < 15) stsX(st ^ 1, xa);                  // safe: readers of st^1 done pre-sync
    }

    // epilogue: fp16 q/k/v
#pragma unroll
    for (int mt = 0; mt < 2; mt++) {
        int r0 = Mbase + wm * 32 + mt * 16 + g;
#pragma unroll
        for (int nt = 0; nt < 6; nt++) {
            int ncol = wn * 48 + nt * 8 + 2 * t4;
            int w = ncol >> 6, cc = ncol & 63;
            __half* outp = (w == 0) ? g_qh : (w == 1) ? g_kh : g_vh;
            *reinterpret_cast<uint32_t*>(outp + (size_t)r0 * HDIM + cc) =
                packh2(acc[mt][nt][0], acc[mt][nt][1]);
            *reinterpret_cast<uint32_t*>(outp + (size_t)(r0 + 8) * HDIM + cc) =
                packh2(acc[mt][nt][2], acc[mt][nt][3]);
        }
    }
}

// ================= Kernel 2: split-K causal attention =================
// 320 CTAs, max 4 key-tile iters, P register-resident, ldmatrix everywhere.
// SMEM words: K0@0(4608) K1@4608 VT0@9216(4352) VT1@13568 Q@17920(4608) -> 90112 B
#define ATTN_SMEM_BYTES 90112

__global__ void __launch_bounds__(256, 2) attn_split()
{
    extern __shared__ uint32_t smw[];
    const uint32_t sb = smem_u32(smw);
    const int t = threadIdx.x, lane = t & 31, warp = t >> 5;
    const int g = lane >> 2, t4 = lane & 3;

    const int bid = blockIdx.x;
    const int b = bid / 40, r = bid % 40;
    int qt, s, ns;
    if (r < 16)      { qt = 12 + (r >> 2);      s = r & 3;        ns = 4; }
    else if (r < 28) { qt = 8 + (r - 16) / 3;   s = (r - 16) % 3; ns = 3; }
    else if (r < 36) { qt = 4 + (r - 28) / 2;   s = (r - 28) % 2; ns = 2; }
    else             { qt = r - 36;             s = 0;            ns = 1; }
    const int len = qt + 1;
    const int k0t = s * len / ns, k1t = (s + 1) * len / ns;
    const int qBase = qt * 128;

    const __half* kg = g_kh + (size_t)b * SEQ * HDIM;
    const __half* vg = g_vh + (size_t)b * SEQ * HDIM;

    // ldmatrix lane offsets (8-row-pair pattern for K/V B-operands)
    const uint32_t lrow8 = (uint32_t)(((lane >> 4) << 3) + (lane & 7));
    const uint32_t lsel  = (uint32_t)(((lane >> 3) & 1) << 4);

    auto issueK = [&](int kt, int st) {
        uint32_t kb = sb + (uint32_t)st * 4608u * 4u;
#pragma unroll
        for (int i = 0; i < 4; i++) {
            int idx = t + i * 256;
            int rr = idx >> 3, j = idx & 7;
            cp16(kb + (uint32_t)(rr * 36 + j * 4) * 4u,
                 kg + (size_t)(kt * 128 + rr) * HDIM + j * 8);
        }
    };
    const int vp = t & 63, vq = t >> 6;
    auto ldgV = [&](int kt, uint4* vr) {
#pragma unroll
        for (int it = 0; it < 2; it++) {
            int q8 = vq + it * 4;
            const __half* src = vg + (size_t)(kt * 128 + 2 * vp) * HDIM + q8 * 8;
            vr[it * 2]     = *reinterpret_cast<const uint4*>(src);
            vr[it * 2 + 1] = *reinterpret_cast<const uint4*>(src + HDIM);
        }
    };
    auto stsV = [&](int st, const uint4* vr) {
        uint32_t* vt = smw + 9216 + st * 4352;
#pragma unroll
        for (int it = 0; it < 2; it++) {
            int q8 = vq + it * 4;
            const uint16_t* r0h = reinterpret_cast<const uint16_t*>(&vr[it * 2]);
            const uint16_t* r1h = reinterpret_cast<const uint16_t*>(&vr[it * 2 + 1]);
#pragma unroll
            for (int i = 0; i < 8; i++)
                vt[(q8 * 8 + i) * 68 + vp] = (uint32_t)r0h[i] | ((uint32_t)r1h[i] << 16);
        }
    };

    // prologue
    issueK(k0t, 0);
    {
        const __half* qg = g_qh + ((size_t)b * SEQ + qBase) * HDIM;
#pragma unroll
        for (int i = 0; i < 4; i++) {
            int idx = t + i * 256;
            int rr = idx >> 3, j = idx & 7;
            cp16(sb + (uint32_t)(17920 + rr * 36 + j * 4) * 4u,
                 qg + (size_t)rr * HDIM + j * 8);
        }
    }
    CP_COMMIT;
    uint4 vr[4];
    ldgV(k0t, vr);
    CP_WAIT0;
    __syncthreads();

    uint32_t qf[4][4];
    {
        const uint32_t Qb = sb + 17920u * 4u;
        const uint32_t qrow = (uint32_t)(warp * 16 + (lane & 15));
        const uint32_t qsel = (uint32_t)((lane >> 4) << 4);
#pragma unroll
        for (int kk = 0; kk < 4; kk++) ldm4(qf[kk], Qb + qrow * 144u + kk * 32u + qsel);
    }
    stsV(0, vr);

    float oacc[8][4];
#pragma unroll
    for (int a = 0; a < 8; a++)
#pragma unroll
        for (int c = 0; c < 4; c++) oacc[a][c] = 0.0f;
    float rs0 = 0.0f, rs1 = 0.0f;
    const int r0l = warp * 16 + g;

    for (int kt = k0t; kt < k1t; kt++) {
        const int st = (kt - k0t) & 1;
        const bool more = (kt + 1 < k1t);
        CP_WAIT0;
        __syncthreads();                               // K(st)+VT(st) visible; prev readers done
        if (more) { issueK(kt + 1, st ^ 1); CP_COMMIT; ldgV(kt + 1, vr); }

        const uint32_t Kb = sb + (uint32_t)st * 4608u * 4u;
        const uint32_t Vb = sb + (9216u + (uint32_t)st * 4352u) * 4u;
        const bool dtile = (kt == qt);

#pragma unroll
        for (int hl = 0; hl < 2; hl++) {
            // ---- S = Q @ K^T (64-key half) ----
            float sacc[8][4];
#pragma unroll
            for (int a = 0; a < 8; a++)
#pragma unroll
                for (int c = 0; c < 4; c++) sacc[a][c] = 0.0f;
#pragma unroll
            for (int p = 0; p < 4; p++) {
                const uint32_t krow = (uint32_t)(hl * 64 + p * 16) + lrow8;
#pragma unroll
                for (int kk = 0; kk < 4; kk++) {
                    uint32_t kb[4];
                    ldm4(kb, Kb + krow * 144u + kk * 32u + lsel);
                    mma16(sacc[2 * p],     qf[kk], kb[0], kb[1]);
                    mma16(sacc[2 * p + 1], qf[kk], kb[2], kb[3]);
                }
            }
            // ---- exp + mask + rowsum (P stays in registers) ----
#pragma unroll
            for (int nt = 0; nt < 8; nt++) {
                int c0 = hl * 64 + nt * 8 + 2 * t4;
                float e0 = __expf(sacc[nt][0] * 0.125f);
                float e1 = __expf(sacc[nt][1] * 0.125f);
                float e2 = __expf(sacc[nt][2] * 0.125f);
                float e3 = __expf(sacc[nt][3] * 0.125f);
                if (dtile) {
                    if (c0     > r0l)     e0 = 0.0f;
                    if (c0 + 1 > r0l)     e1 = 0.0f;
                    if (c0     > r0l + 8) e2 = 0.0f;
                    if (c0 + 1 > r0l + 8) e3 = 0.0f;
                }
                rs0 += e0 + e1;
                rs1 += e2 + e3;
                sacc[nt][0] = e0; sacc[nt][1] = e1;
                sacc[nt][2] = e2; sacc[nt][3] = e3;
            }
            // ---- O += P @ V (A-frag built from sacc) ----
#pragma unroll
            for (int kk = 0; kk < 4; kk++) {
                uint32_t af[4];
                af[0] = packh2(sacc[2 * kk][0],     sacc[2 * kk][1]);
                af[1] = packh2(sacc[2 * kk][2],     sacc[2 * kk][3]);
                af[2] = packh2(sacc[2 * kk + 1][0], sacc[2 * kk + 1][1]);
                af[3] = packh2(sacc[2 * kk + 1][2], sacc[2 * kk + 1][3]);
#pragma unroll
                for (int p = 0; p < 4; p++) {
                    uint32_t vb[4];
                    ldm4(vb, Vb + ((uint32_t)(p * 16) + lrow8) * 272u
                             + (uint32_t)(hl * 128 + kk * 32) + lsel);
                    mma16(oacc[2 * p],     af, vb[0], vb[1]);
                    mma16(oacc[2 * p + 1], af, vb[2], vb[3]);
                }
            }
        }
        if (more) stsV(st ^ 1, vr);                    // safe: st^1 readers done pre-sync
    }

    // ---- partial epilogue ----
    rs0 += __shfl_xor_sync(0xffffffffu, rs0, 1);
    rs0 += __shfl_xor_sync(0xffffffffu, rs0, 2);
    rs1 += __shfl_xor_sync(0xffffffffu, rs1, 1);
    rs1 += __shfl_xor_sync(0xffffffffu, rs1, 2);

    float* po = g_partO[s] + ((size_t)b * SEQ + qBase + r0l) * HDIM;
#pragma unroll
    for (int nt = 0; nt < 8; nt++) {
        int cc = nt * 8 + 2 * t4;
        float2 v0 = { oacc[nt][0], oacc[nt][1] };
        *reinterpret_cast<float2*>(po + cc) = v0;
        float2 v1 = { oacc[nt][2], oacc[nt][3] };
        *reinterpret_cast<float2*>(po + (size_t)8 * HDIM + cc) = v1;
    }
    if (t4 == 0) {
        g_partL[s][(size_t)b * SEQ + qBase + r0l]     = rs0;
        g_partL[s][(size_t)b * SEQ + qBase + r0l + 8] = rs1;
    }
}

// ================= Kernel 3: combine splits + normalize =================
__global__ void __launch_bounds__(256) combine_kernel(float* __restrict__ out)
{
    int gid = blockIdx.x * 256 + threadIdx.x;
    int row = gid >> 4;
    int qt = (row & (SEQ - 1)) >> 7;
    int ns = (qt + 4) / 4;

    float4 o = reinterpret_cast<const float4*>(g_partO[0])[gid];
    float  l = g_partL[0][row];
#pragma unroll
    for (int s = 1; s < 4; s++) {
        if (ns > s) {
            float4 os = reinterpret_cast<const float4*>(g_partO[s])[gid];
            o.x += os.x; o.y += os.y; o.z += os.z; o.w += os.w;
            l += g_partL[s][row];
        }
    }
    float inv = 1.0f / l;
    o.x *= inv; o.y *= inv; o.z *= inv; o.w *= inv;
    reinterpret_cast<float4*>(out)[gid] = o;
}

// ---------------- launch ----------------
extern "C" void kernel_launch(void* const* d_in, const int* in_sizes, int n_in,
                              void* d_out, int out_size)
{
    const float* x  = (const float*)d_in[0];
    const float* Wq = (const float*)d_in[1];
    const float* Wk = (const float*)d_in[2];
    const float* Wv = (const float*)d_in[3];
    float* out = (float*)d_out;

    wt_kernel<<<dim3(CDIM / 32, HDIM / 32, 3), dim3(32, 32)>>>(Wq, Wk, Wv);

    cudaFuncSetAttribute(qkv_mma, cudaFuncAttributeMaxDynamicSharedMemorySize,
                         QKV_SMEM_BYTES);
    qkv_mma<<<(BATCH * SEQ) / 64, 256, QKV_SMEM_BYTES>>>(x);

    cudaFuncSetAttribute(attn_split, cudaFuncAttributeMaxDynamicSharedMemorySize,
                         ATTN_SMEM_BYTES);
    attn_split<<<320, 256, ATTN_SMEM_BYTES>>>();

    combine_kernel<<<(BATCH * SEQ * HDIM / 4) / 256, 256>>>(out);
}

// round 12
// speedup vs baseline: 1.8157x; 1.0639x over previous
#include <cuda_runtime.h>
#include <cuda_fp16.h>
#include <cstdint>

#define BATCH 8
#define SEQ   2048
#define CDIM  1024
#define HDIM  64

// ---------------- persistent scratch ----------------
__device__ __half g_wth[3 * HDIM * CDIM];          // [192 n][1024 k] fp16 W^T
__device__ __half g_qh[BATCH * SEQ * HDIM];
__device__ __half g_kh[BATCH * SEQ * HDIM];
__device__ __half g_vh[BATCH * SEQ * HDIM];
__device__ float  g_partO[4][BATCH * SEQ * HDIM];
__device__ float  g_partL[4][BATCH * SEQ];

// ---------------- helpers ----------------
__device__ __forceinline__ uint32_t smem_u32(const void* p) {
    uint32_t a;
    asm("{ .reg .u64 t; cvta.to.shared.u64 t, %1; cvt.u32.u64 %0, t; }" : "=r"(a) : "l"(p));
    return a;
}
__device__ __forceinline__ void cp16(uint32_t dst, const void* src) {
    asm volatile("cp.async.cg.shared.global [%0], [%1], 16;" :: "r"(dst), "l"(src));
}
#define CP_COMMIT asm volatile("cp.async.commit_group;" ::: "memory")
#define CP_WAIT0  asm volatile("cp.async.wait_group 0;" ::: "memory")

__device__ __forceinline__ uint32_t packh2(float lo, float hi) {
    uint32_t d;
    asm("cvt.rn.f16x2.f32 %0, %1, %2;" : "=r"(d) : "f"(hi), "f"(lo));
    return d;
}
__device__ __forceinline__ void mma16(float* c, const uint32_t* a, uint32_t b0, uint32_t b1) {
    asm volatile(
        "mma.sync.aligned.m16n8k16.row.col.f32.f16.f16.f32 "
        "{%0,%1,%2,%3}, {%4,%5,%6,%7}, {%8,%9}, {%0,%1,%2,%3};"
        : "+f"(c[0]), "+f"(c[1]), "+f"(c[2]), "+f"(c[3])
        : "r"(a[0]), "r"(a[1]), "r"(a[2]), "r"(a[3]), "r"(b0), "r"(b1));
}
__device__ __forceinline__ void ldm4(uint32_t* r, uint32_t addr) {
    asm volatile("ldmatrix.sync.aligned.m8n8.x4.shared.b16 {%0,%1,%2,%3}, [%4];"
                 : "=r"(r[0]), "=r"(r[1]), "=r"(r[2]), "=r"(r[3]) : "r"(addr));
}
__device__ __forceinline__ void ldm4t(uint32_t* r, uint32_t addr) {
    asm volatile("ldmatrix.sync.aligned.m8n8.x4.trans.shared.b16 {%0,%1,%2,%3}, [%4];"
                 : "=r"(r[0]), "=r"(r[1]), "=r"(r[2]), "=r"(r[3]) : "r"(addr));
}

// ================= Kernel 0: W transpose + fp16 =================
__global__ void wt_kernel(const float* __restrict__ Wq,
                          const float* __restrict__ Wk,
                          const float* __restrict__ Wv)
{
    const float* W = (blockIdx.z == 0) ? Wq : (blockIdx.z == 1) ? Wk : Wv;
    __shared__ float tile[32][33];
    int c0 = blockIdx.x * 32, h0 = blockIdx.y * 32;
    tile[threadIdx.y][threadIdx.x] = W[(size_t)(c0 + threadIdx.y) * HDIM + h0 + threadIdx.x];
    __syncthreads();
    g_wth[(size_t)blockIdx.z * HDIM * CDIM + (size_t)(h0 + threadIdx.y) * CDIM + c0 + threadIdx.x] =
        __float2half_rn(tile[threadIdx.x][threadIdx.y]);
}

// ================= Kernel 1: fused QKV projection =================
// grid 256: 64-row M-tile. K-chunk 64 (4 k16 steps), double-buffered, 1 sync/iter.
// SMEM words: A0[64*36]@0  A1@2304  B0[192*36]@4608  B1@11520  -> 73728 B
#define QKV_SMEM_BYTES 73728

__global__ void __launch_bounds__(256, 2) qkv_mma(const float* __restrict__ x)
{
    extern __shared__ uint32_t smw[];
    const uint32_t sb = smem_u32(smw);
    const int t = threadIdx.x, lane = t & 31, warp = t >> 5;
    const int g = lane >> 2, t4 = lane & 3;
    const int wm = warp >> 2, wn = warp & 3;           // 2M x 4N warps
    const int Mbase = blockIdx.x * 64;

    const uint32_t arow = lane & 15;
    const uint32_t asel = (uint32_t)((lane >> 4) << 4);
    const uint32_t nrow = (uint32_t)(((lane >> 4) << 3) + (lane & 7));
    const uint32_t bsel = (uint32_t)(((lane >> 3) & 1) << 4);

    float acc[2][6][4];
#pragma unroll
    for (int a = 0; a < 2; a++)
#pragma unroll
        for (int b = 0; b < 6; b++)
#pragma unroll
            for (int c = 0; c < 4; c++) acc[a][b][c] = 0.0f;

    const int xr = t >> 2, xj = t & 3;

    auto ldgX = [&](int c, float4* v) {
        const float* src = x + (size_t)(Mbase + xr) * CDIM + c * 64 + xj * 16;
#pragma unroll
        for (int i = 0; i < 4; i++) v[i] = *reinterpret_cast<const float4*>(src + i * 4);
    };
    auto stsX = [&](int st, const float4* v) {
        uint4 h0, h1;
        h0.x = packh2(v[0].x, v[0].y); h0.y = packh2(v[0].z, v[0].w);
        h0.z = packh2(v[1].x, v[1].y); h0.w = packh2(v[1].z, v[1].w);
        h1.x = packh2(v[2].x, v[2].y); h1.y = packh2(v[2].z, v[2].w);
        h1.z = packh2(v[3].x, v[3].y); h1.w = packh2(v[3].z, v[3].w);
        *reinterpret_cast<uint4*>(smw + st * 2304 + xr * 36 + xj * 8)     = h0;
        *reinterpret_cast<uint4*>(smw + st * 2304 + xr * 36 + xj * 8 + 4) = h1;
    };
    auto issueB = [&](int c, int st) {
        uint32_t bb = sb + (4608u + (uint32_t)st * 6912u) * 4u;
#pragma unroll
        for (int i = 0; i < 6; i++) {
            int idx = t + i * 256;
            int n = idx >> 3, j = idx & 7;
            cp16(bb + (uint32_t)(n * 36 + j * 4) * 4u,
                 g_wth + (size_t)n * CDIM + c * 64 + j * 8);
        }
    };

    float4 xa[4];
    ldgX(0, xa); stsX(0, xa);
    issueB(0, 0); CP_COMMIT;

    for (int c = 0; c < 16; c++) {
        const int st = c & 1;
        CP_WAIT0;
        __syncthreads();
        if (c < 15) { issueB(c + 1, st ^ 1); CP_COMMIT; ldgX(c + 1, xa); }

        const uint32_t Ab = sb + (uint32_t)st * 2304u * 4u;
        const uint32_t Bb = sb + (4608u + (uint32_t)st * 6912u) * 4u;

#pragma unroll
        for (int kk = 0; kk < 4; kk++) {
            uint32_t af0[4], af1[4];
            ldm4(af0, Ab + (wm * 32 +      arow) * 144u + kk * 32u + asel);
            ldm4(af1, Ab + (wm * 32 + 16 + arow) * 144u + kk * 32u + asel);
#pragma unroll
            for (int j = 0; j < 3; j++) {
                uint32_t bf[4];
                ldm4(bf, Bb + (wn * 48 + j * 16 + nrow) * 144u + kk * 32u + bsel);
                mma16(acc[0][2 * j],     af0, bf[0], bf[1]);
                mma16(acc[0][2 * j + 1], af0, bf[2], bf[3]);
                mma16(acc[1][2 * j],     af1, bf[0], bf[1]);
                mma16(acc[1][2 * j + 1], af1, bf[2], bf[3]);
            }
        }
        if (c < 15) stsX(st ^ 1, xa);
    }

#pragma unroll
    for (int mt = 0; mt < 2; mt++) {
        int r0 = Mbase + wm * 32 + mt * 16 + g;
#pragma unroll
        for (int nt = 0; nt < 6; nt++) {
            int ncol = wn * 48 + nt * 8 + 2 * t4;
            int w = ncol >> 6, cc = ncol & 63;
            __half* outp = (w == 0) ? g_qh : (w == 1) ? g_kh : g_vh;
            *reinterpret_cast<uint32_t*>(outp + (size_t)r0 * HDIM + cc) =
                packh2(acc[mt][nt][0], acc[mt][nt][1]);
            *reinterpret_cast<uint32_t*>(outp + (size_t)(r0 + 8) * HDIM + cc) =
                packh2(acc[mt][nt][2], acc[mt][nt][3]);
        }
    }
}

// ================= Kernel 2: split-K causal attention =================
// 320 CTAs, max 4 key-tile iters. K AND V row-major via cp.async (double-buffered);
// V transposed in the LSU via ldmatrix.x4.trans. P register-resident.
// SMEM words: K0@0 K1@4608 V0@9216 V1@13824 Q@18432 (each 4608) -> 92160 B
#define ATTN_SMEM_BYTES 92160

__global__ void __launch_bounds__(256, 2) attn_split()
{
    extern __shared__ uint32_t smw[];
    const uint32_t sb = smem_u32(smw);
    const int t = threadIdx.x, lane = t & 31, warp = t >> 5;
    const int g = lane >> 2, t4 = lane & 3;

    const int bid = blockIdx.x;
    const int b = bid / 40, r = bid % 40;
    int qt, s, ns;
    if (r < 16)      { qt = 12 + (r >> 2);      s = r & 3;        ns = 4; }
    else if (r < 28) { qt = 8 + (r - 16) / 3;   s = (r - 16) % 3; ns = 3; }
    else if (r < 36) { qt = 4 + (r - 28) / 2;   s = (r - 28) % 2; ns = 2; }
    else             { qt = r - 36;             s = 0;            ns = 1; }
    const int len = qt + 1;
    const int k0t = s * len / ns, k1t = (s + 1) * len / ns;
    const int qBase = qt * 128;

    const __half* kg = g_kh + (size_t)b * SEQ * HDIM;
    const __half* vg = g_vh + (size_t)b * SEQ * HDIM;

    // K (non-trans B): lanes (0-7,8-15)->rows 0-7, (16-31)->rows 8-15; 16B col sel by bit3
    const uint32_t lrow8 = (uint32_t)(((lane >> 4) << 3) + (lane & 7));
    const uint32_t lsel  = (uint32_t)(((lane >> 3) & 1) << 4);
    // V (trans B): lanes (0-7)->k0-7,n0; (8-15)->k8-15,n0; (16-23)->k0-7,n8; (24-31)->k8-15,n8
    const uint32_t vrow  = (uint32_t)((((lane >> 3) & 1) << 3) + (lane & 7));
    const uint32_t vsel  = (uint32_t)((lane >> 4) << 4);

    auto issueKV = [&](int kt, int st) {
        uint32_t kb = sb + (uint32_t)st * 4608u * 4u;
        uint32_t vb = sb + (9216u + (uint32_t)st * 4608u) * 4u;
#pragma unroll
        for (int i = 0; i < 4; i++) {
            int idx = t + i * 256;
            int rr = idx >> 3, j = idx & 7;
            cp16(kb + (uint32_t)(rr * 36 + j * 4) * 4u,
                 kg + (size_t)(kt * 128 + rr) * HDIM + j * 8);
            cp16(vb + (uint32_t)(rr * 36 + j * 4) * 4u,
                 vg + (size_t)(kt * 128 + rr) * HDIM + j * 8);
        }
    };

    // prologue: K+V(k0t) and Q
    issueKV(k0t, 0);
    {
        const __half* qg = g_qh + ((size_t)b * SEQ + qBase) * HDIM;
#pragma unroll
        for (int i = 0; i < 4; i++) {
            int idx = t + i * 256;
            int rr = idx >> 3, j = idx & 7;
            cp16(sb + (uint32_t)(18432 + rr * 36 + j * 4) * 4u,
                 qg + (size_t)rr * HDIM + j * 8);
        }
    }
    CP_COMMIT;
    CP_WAIT0;
    __syncthreads();

    uint32_t qf[4][4];
    {
        const uint32_t Qb = sb + 18432u * 4u;
        const uint32_t qrow = (uint32_t)(warp * 16 + (lane & 15));
        const uint32_t qsel = (uint32_t)((lane >> 4) << 4);
#pragma unroll
        for (int kk = 0; kk < 4; kk++) ldm4(qf[kk], Qb + qrow * 144u + kk * 32u + qsel);
    }

    float oacc[8][4];
#pragma unroll
    for (int a = 0; a < 8; a++)
#pragma unroll
        for (int c = 0; c < 4; c++) oacc[a][c] = 0.0f;
    float rs0 = 0.0f, rs1 = 0.0f;
    const int r0l = warp * 16 + g;

    for (int kt = k0t; kt < k1t; kt++) {
        const int st = (kt - k0t) & 1;
        const bool more = (kt + 1 < k1t);
        if (kt > k0t) { CP_WAIT0; __syncthreads(); }
        if (more) { issueKV(kt + 1, st ^ 1); CP_COMMIT; }

        const uint32_t Kb = sb + (uint32_t)st * 4608u * 4u;
        const uint32_t Vb = sb + (9216u + (uint32_t)st * 4608u) * 4u;
        const bool dtile = (kt == qt);

#pragma unroll
        for (int hl = 0; hl < 2; hl++) {
            // ---- S = Q @ K^T (64-key half) ----
            float sacc[8][4];
#pragma unroll
            for (int a = 0; a < 8; a++)
#pragma unroll
                for (int c = 0; c < 4; c++) sacc[a][c] = 0.0f;
#pragma unroll
            for (int p = 0; p < 4; p++) {
                const uint32_t krow = (uint32_t)(hl * 64 + p * 16) + lrow8;
#pragma unroll
                for (int kk = 0; kk < 4; kk++) {
                    uint32_t kb[4];
                    ldm4(kb, Kb + krow * 144u + kk * 32u + lsel);
                    mma16(sacc[2 * p],     qf[kk], kb[0], kb[1]);
                    mma16(sacc[2 * p + 1], qf[kk], kb[2], kb[3]);
                }
            }
            // ---- exp + mask + rowsum (registers only) ----
#pragma unroll
            for (int nt = 0; nt < 8; nt++) {
                int c0 = hl * 64 + nt * 8 + 2 * t4;
                float e0 = __expf(sacc[nt][0] * 0.125f);
                float e1 = __expf(sacc[nt][1] * 0.125f);
                float e2 = __expf(sacc[nt][2] * 0.125f);
                float e3 = __expf(sacc[nt][3] * 0.125f);
                if (dtile) {
                    if (c0     > r0l)     e0 = 0.0f;
                    if (c0 + 1 > r0l)     e1 = 0.0f;
                    if (c0     > r0l + 8) e2 = 0.0f;
                    if (c0 + 1 > r0l + 8) e3 = 0.0f;
                }
                rs0 += e0 + e1;
                rs1 += e2 + e3;
                sacc[nt][0] = e0; sacc[nt][1] = e1;
                sacc[nt][2] = e2; sacc[nt][3] = e3;
            }
            // ---- O += P @ V (V transposed by ldmatrix.trans) ----
#pragma unroll
            for (int kk = 0; kk < 4; kk++) {
                uint32_t af[4];
                af[0] = packh2(sacc[2 * kk][0],     sacc[2 * kk][1]);
                af[1] = packh2(sacc[2 * kk][2],     sacc[2 * kk][3]);
                af[2] = packh2(sacc[2 * kk + 1][0], sacc[2 * kk + 1][1]);
                af[3] = packh2(sacc[2 * kk + 1][2], sacc[2 * kk + 1][3]);
                const uint32_t vr = (uint32_t)(hl * 64 + kk * 16) + vrow;
#pragma unroll
                for (int p = 0; p < 4; p++) {
                    uint32_t vb[4];
                    ldm4t(vb, Vb + vr * 144u + (uint32_t)(p * 32) + vsel);
                    mma16(oacc[2 * p],     af, vb[0], vb[1]);
                    mma16(oacc[2 * p + 1], af, vb[2], vb[3]);
                }
            }
        }
    }

    // ---- partial epilogue ----
    rs0 += __shfl_xor_sync(0xffffffffu, rs0, 1);
    rs0 += __shfl_xor_sync(0xffffffffu, rs0, 2);
    rs1 += __shfl_xor_sync(0xffffffffu, rs1, 1);
    rs1 += __shfl_xor_sync(0xffffffffu, rs1, 2);

    float* po = g_partO[s] + ((size_t)b * SEQ + qBase + r0l) * HDIM;
#pragma unroll
    for (int nt = 0; nt < 8; nt++) {
        int cc = nt * 8 + 2 * t4;
        float2 v0 = { oacc[nt][0], oacc[nt][1] };
        *reinterpret_cast<float2*>(po + cc) = v0;
        float2 v1 = { oacc[nt][2], oacc[nt][3] };
        *reinterpret_cast<float2*>(po + (size_t)8 * HDIM + cc) = v1;
    }
    if (t4 == 0) {
        g_partL[s][(size_t)b * SEQ + qBase + r0l]     = rs0;
        g_partL[s][(size_t)b * SEQ + qBase + r0l + 8] = rs1;
    }
}

// ================= Kernel 3: combine splits + normalize =================
// 2 float4 per thread (same row), higher ILP.
__global__ void __launch_bounds__(256) combine_kernel(float* __restrict__ out)
{
    int base = (blockIdx.x * 256 + threadIdx.x) * 2;   // two consecutive float4
    int row = base >> 4;
    int qt = (row & (SEQ - 1)) >> 7;
    int ns = (qt + 4) / 4;

    float4 o0 = reinterpret_cast<const float4*>(g_partO[0])[base];
    float4 o1 = reinterpret_cast<const float4*>(g_partO[0])[base + 1];
    float  l  = g_partL[0][row];
#pragma unroll
    for (int s = 1; s < 4; s++) {
        if (ns > s) {
            float4 a = reinterpret_cast<const float4*>(g_partO[s])[base];
            float4 c = reinterpret_cast<const float4*>(g_partO[s])[base + 1];
            o0.x += a.x; o0.y += a.y; o0.z += a.z; o0.w += a.w;
            o1.x += c.x; o1.y += c.y; o1.z += c.z; o1.w += c.w;
            l += g_partL[s][row];
        }
    }
    float inv = 1.0f / l;
    o0.x *= inv; o0.y *= inv; o0.z *= inv; o0.w *= inv;
    o1.x *= inv; o1.y *= inv; o1.z *= inv; o1.w *= inv;
    reinterpret_cast<float4*>(out)[base]     = o0;
    reinterpret_cast<float4*>(out)[base + 1] = o1;
}

// ---------------- launch ----------------
extern "C" void kernel_launch(void* const* d_in, const int* in_sizes, int n_in,
                              void* d_out, int out_size)
{
    const float* x  = (const float*)d_in[0];
    const float* Wq = (const float*)d_in[1];
    const float* Wk = (const float*)d_in[2];
    const float* Wv = (const float*)d_in[3];
    float* out = (float*)d_out;

    wt_kernel<<<dim3(CDIM / 32, HDIM / 32, 3), dim3(32, 32)>>>(Wq, Wk, Wv);

    cudaFuncSetAttribute(qkv_mma, cudaFuncAttributeMaxDynamicSharedMemorySize,
                         QKV_SMEM_BYTES);
    qkv_mma<<<(BATCH * SEQ) / 64, 256, QKV_SMEM_BYTES>>>(x);

    cudaFuncSetAttribute(attn_split, cudaFuncAttributeMaxDynamicSharedMemorySize,
                         ATTN_SMEM_BYTES);
    attn_split<<<320, 256, ATTN_SMEM_BYTES>>>();

    combine_kernel<<<(BATCH * SEQ * HDIM / 8) / 256, 256>>>(out);
}

// round 13
// speedup vs baseline: 1.8720x; 1.0310x over previous
#include <cuda_runtime.h>
#include <cuda_fp16.h>
#include <cstdint>

#define BATCH 8
#define SEQ   2048
#define CDIM  1024
#define HDIM  64

// ---------------- persistent scratch ----------------
__device__ __half g_wth[3 * HDIM * CDIM];          // [192 n][1024 k] fp16 W^T
__device__ __half g_qh[BATCH * SEQ * HDIM];        // q PRE-SCALED by 0.125*log2(e)
__device__ __half g_kh[BATCH * SEQ * HDIM];
__device__ __half g_vh[BATCH * SEQ * HDIM];
__device__ float  g_partO[4][BATCH * SEQ * HDIM];
__device__ float  g_partL[4][BATCH * SEQ];

#define QSCALE 0.18033688011112042f   /* 0.125 * log2(e) */
#define ONESH2 0x3C003C00u            /* {1.0h, 1.0h}     */

// ---------------- helpers ----------------
__device__ __forceinline__ uint32_t smem_u32(const void* p) {
    uint32_t a;
    asm("{ .reg .u64 t; cvta.to.shared.u64 t, %1; cvt.u32.u64 %0, t; }" : "=r"(a) : "l"(p));
    return a;
}
__device__ __forceinline__ void cp16(uint32_t dst, const void* src) {
    asm volatile("cp.async.cg.shared.global [%0], [%1], 16;" :: "r"(dst), "l"(src));
}
#define CP_COMMIT asm volatile("cp.async.commit_group;" ::: "memory")
#define CP_WAIT0  asm volatile("cp.async.wait_group 0;" ::: "memory")

__device__ __forceinline__ uint32_t packh2(float lo, float hi) {
    uint32_t d;
    asm("cvt.rn.f16x2.f32 %0, %1, %2;" : "=r"(d) : "f"(hi), "f"(lo));
    return d;
}
__device__ __forceinline__ uint32_t ex2h2(uint32_t x) {
    uint32_t d;
    asm("ex2.approx.f16x2 %0, %1;" : "=r"(d) : "r"(x));
    return d;
}
__device__ __forceinline__ void mma16(float* c, const uint32_t* a, uint32_t b0, uint32_t b1) {
    asm volatile(
        "mma.sync.aligned.m16n8k16.row.col.f32.f16.f16.f32 "
        "{%0,%1,%2,%3}, {%4,%5,%6,%7}, {%8,%9}, {%0,%1,%2,%3};"
        : "+f"(c[0]), "+f"(c[1]), "+f"(c[2]), "+f"(c[3])
        : "r"(a[0]), "r"(a[1]), "r"(a[2]), "r"(a[3]), "r"(b0), "r"(b1));
}
__device__ __forceinline__ void ldm4(uint32_t* r, uint32_t addr) {
    asm volatile("ldmatrix.sync.aligned.m8n8.x4.shared.b16 {%0,%1,%2,%3}, [%4];"
                 : "=r"(r[0]), "=r"(r[1]), "=r"(r[2]), "=r"(r[3]) : "r"(addr));
}
__device__ __forceinline__ void ldm4t(uint32_t* r, uint32_t addr) {
    asm volatile("ldmatrix.sync.aligned.m8n8.x4.trans.shared.b16 {%0,%1,%2,%3}, [%4];"
                 : "=r"(r[0]), "=r"(r[1]), "=r"(r[2]), "=r"(r[3]) : "r"(addr));
}

// ================= Kernel 0: W transpose + fp16 =================
__global__ void wt_kernel(const float* __restrict__ Wq,
                          const float* __restrict__ Wk,
                          const float* __restrict__ Wv)
{
    const float* W = (blockIdx.z == 0) ? Wq : (blockIdx.z == 1) ? Wk : Wv;
    __shared__ float tile[32][33];
    int c0 = blockIdx.x * 32, h0 = blockIdx.y * 32;
    tile[threadIdx.y][threadIdx.x] = W[(size_t)(c0 + threadIdx.y) * HDIM + h0 + threadIdx.x];
    __syncthreads();
    g_wth[(size_t)blockIdx.z * HDIM * CDIM + (size_t)(h0 + threadIdx.y) * CDIM + c0 + threadIdx.x] =
        __float2half_rn(tile[threadIdx.x][threadIdx.y]);
}

// ================= Kernel 1: fused QKV projection =================
// grid 128, 512 threads: 128-row M-tile (halves W L2 traffic vs 64-row tiles).
// 16 warps as 4M x 4N (warp tile 32x48). K-chunk 64, double-buffered, 1 sync/iter.
// SMEM words: A0[128*36]@0  A1@4608  B0[192*36]@9216  B1@16128  -> 92160 B
#define QKV_SMEM_BYTES 92160

__global__ void __launch_bounds__(512, 1) qkv_mma(const float* __restrict__ x)
{
    extern __shared__ uint32_t smw[];
    const uint32_t sb = smem_u32(smw);
    const int t = threadIdx.x, lane = t & 31, warp = t >> 5;
    const int g = lane >> 2, t4 = lane & 3;
    const int wm = warp >> 2, wn = warp & 3;           // 4M x 4N warps
    const int Mbase = blockIdx.x * 128;

    const uint32_t arow = lane & 15;
    const uint32_t asel = (uint32_t)((lane >> 4) << 4);
    const uint32_t nrow = (uint32_t)(((lane >> 4) << 3) + (lane & 7));
    const uint32_t bsel = (uint32_t)(((lane >> 3) & 1) << 4);

    float acc[2][6][4];
#pragma unroll
    for (int a = 0; a < 2; a++)
#pragma unroll
        for (int b = 0; b < 6; b++)
#pragma unroll
            for (int c = 0; c < 4; c++) acc[a][b][c] = 0.0f;

    const int xr = t >> 2, xj = t & 3;                 // 128 rows x 4 col-groups

    auto ldgX = [&](int c, float4* v) {
        const float* src = x + (size_t)(Mbase + xr) * CDIM + c * 64 + xj * 16;
#pragma unroll
        for (int i = 0; i < 4; i++) v[i] = *reinterpret_cast<const float4*>(src + i * 4);
    };
    auto stsX = [&](int st, const float4* v) {
        uint4 h0, h1;
        h0.x = packh2(v[0].x, v[0].y); h0.y = packh2(v[0].z, v[0].w);
        h0.z = packh2(v[1].x, v[1].y); h0.w = packh2(v[1].z, v[1].w);
        h1.x = packh2(v[2].x, v[2].y); h1.y = packh2(v[2].z, v[2].w);
        h1.z = packh2(v[3].x, v[3].y); h1.w = packh2(v[3].z, v[3].w);
        *reinterpret_cast<uint4*>(smw + st * 4608 + xr * 36 + xj * 8)     = h0;
        *reinterpret_cast<uint4*>(smw + st * 4608 + xr * 36 + xj * 8 + 4) = h1;
    };
    auto issueB = [&](int c, int st) {
        uint32_t bb = sb + (9216u + (uint32_t)st * 6912u) * 4u;
#pragma unroll
        for (int i = 0; i < 3; i++) {                  // 192 rows x 64 halves = 1536 f4
            int idx = t + i * 512;
            int n = idx >> 3, j = idx & 7;
            cp16(bb + (uint32_t)(n * 36 + j * 4) * 4u,
                 g_wth + (size_t)n * CDIM + c * 64 + j * 8);
        }
    };

    float4 xa[4];
    ldgX(0, xa); stsX(0, xa);
    issueB(0, 0); CP_COMMIT;

    for (int c = 0; c < 16; c++) {
        const int st = c & 1;
        CP_WAIT0;
        __syncthreads();
        if (c < 15) { issueB(c + 1, st ^ 1); CP_COMMIT; ldgX(c + 1, xa); }

        const uint32_t Ab = sb + (uint32_t)st * 4608u * 4u;
        const uint32_t Bb = sb + (9216u + (uint32_t)st * 6912u) * 4u;

#pragma unroll
        for (int kk = 0; kk < 4; kk++) {
            uint32_t af0[4], af1[4];
            ldm4(af0, Ab + (wm * 32 +      arow) * 144u + kk * 32u + asel);
            ldm4(af1, Ab + (wm * 32 + 16 + arow) * 144u + kk * 32u + asel);
#pragma unroll
            for (int j = 0; j < 3; j++) {
                uint32_t bf[4];
                ldm4(bf, Bb + (wn * 48 + j * 16 + nrow) * 144u + kk * 32u + bsel);
                mma16(acc[0][2 * j],     af0, bf[0], bf[1]);
                mma16(acc[0][2 * j + 1], af0, bf[2], bf[3]);
                mma16(acc[1][2 * j],     af1, bf[0], bf[1]);
                mma16(acc[1][2 * j + 1], af1, bf[2], bf[3]);
            }
        }
        if (c < 15) stsX(st ^ 1, xa);
    }

    // epilogue: q is pre-scaled by QSCALE (softmax scale folded into log2 domain)
#pragma unroll
    for (int mt = 0; mt < 2; mt++) {
        int r0 = Mbase + wm * 32 + mt * 16 + g;
#pragma unroll
        for (int nt = 0; nt < 6; nt++) {
            int ncol = wn * 48 + nt * 8 + 2 * t4;
            int w = ncol >> 6, cc = ncol & 63;
            __half* outp = (w == 0) ? g_qh : (w == 1) ? g_kh : g_vh;
            float sc = (w == 0) ? QSCALE : 1.0f;
            *reinterpret_cast<uint32_t*>(outp + (size_t)r0 * HDIM + cc) =
                packh2(acc[mt][nt][0] * sc, acc[mt][nt][1] * sc);
            *reinterpret_cast<uint32_t*>(outp + (size_t)(r0 + 8) * HDIM + cc) =
                packh2(acc[mt][nt][2] * sc, acc[mt][nt][3] * sc);
        }
    }
}

// ================= Kernel 2: split-K causal attention =================
// 320 CTAs, max 4 key-tile iters. exp via ex2.approx.f16x2 (S already log2-scaled
// through Q). Row-sum l computed by ones-column MMA on the tensor pipe.
// ns==1 CTAs write normalized output directly.
// SMEM words: K0@0 K1@4608 V0@9216 V1@13824 Q@18432 (each 4608) -> 92160 B
#define ATTN_SMEM_BYTES 92160

__global__ void __launch_bounds__(256, 2) attn_split(float* __restrict__ outp)
{
    extern __shared__ uint32_t smw[];
    const uint32_t sb = smem_u32(smw);
    const int t = threadIdx.x, lane = t & 31, warp = t >> 5;
    const int g = lane >> 2, t4 = lane & 3;

    const int bid = blockIdx.x;
    const int b = bid / 40, r = bid % 40;
    int qt, s, ns;
    if (r < 16)      { qt = 12 + (r >> 2);      s = r & 3;        ns = 4; }
    else if (r < 28) { qt = 8 + (r - 16) / 3;   s = (r - 16) % 3; ns = 3; }
    else if (r < 36) { qt = 4 + (r - 28) / 2;   s = (r - 28) % 2; ns = 2; }
    else             { qt = r - 36;             s = 0;            ns = 1; }
    const int len = qt + 1;
    const int k0t = s * len / ns, k1t = (s + 1) * len / ns;
    const int qBase = qt * 128;

    const __half* kg = g_kh + (size_t)b * SEQ * HDIM;
    const __half* vg = g_vh + (size_t)b * SEQ * HDIM;

    const uint32_t lrow8 = (uint32_t)(((lane >> 4) << 3) + (lane & 7));
    const uint32_t lsel  = (uint32_t)(((lane >> 3) & 1) << 4);
    const uint32_t vrow  = (uint32_t)((((lane >> 3) & 1) << 3) + (lane & 7));
    const uint32_t vsel  = (uint32_t)((lane >> 4) << 4);

    auto issueKV = [&](int kt, int st) {
        uint32_t kb = sb + (uint32_t)st * 4608u * 4u;
        uint32_t vb = sb + (9216u + (uint32_t)st * 4608u) * 4u;
#pragma unroll
        for (int i = 0; i < 4; i++) {
            int idx = t + i * 256;
            int rr = idx >> 3, j = idx & 7;
            cp16(kb + (uint32_t)(rr * 36 + j * 4) * 4u,
                 kg + (size_t)(kt * 128 + rr) * HDIM + j * 8);
            cp16(vb + (uint32_t)(rr * 36 + j * 4) * 4u,
                 vg + (size_t)(kt * 128 + rr) * HDIM + j * 8);
        }
    };

    issueKV(k0t, 0);
    {
        const __half* qg = g_qh + ((size_t)b * SEQ + qBase) * HDIM;
#pragma unroll
        for (int i = 0; i < 4; i++) {
            int idx = t + i * 256;
            int rr = idx >> 3, j = idx & 7;
            cp16(sb + (uint32_t)(18432 + rr * 36 + j * 4) * 4u,
                 qg + (size_t)rr * HDIM + j * 8);
        }
    }
    CP_COMMIT;
    CP_WAIT0;
    __syncthreads();

    uint32_t qf[4][4];
    {
        const uint32_t Qb = sb + 18432u * 4u;
        const uint32_t qrow = (uint32_t)(warp * 16 + (lane & 15));
        const uint32_t qsel = (uint32_t)((lane >> 4) << 4);
#pragma unroll
        for (int kk = 0; kk < 4; kk++) ldm4(qf[kk], Qb + qrow * 144u + kk * 32u + qsel);
    }

    float oacc[8][4];
#pragma unroll
    for (int a = 0; a < 8; a++)
#pragma unroll
        for (int c = 0; c < 4; c++) oacc[a][c] = 0.0f;
    float lacc[4] = {0.0f, 0.0f, 0.0f, 0.0f};
    const int r0l = warp * 16 + g;

    for (int kt = k0t; kt < k1t; kt++) {
        const int st = (kt - k0t) & 1;
        const bool more = (kt + 1 < k1t);
        if (kt > k0t) { CP_WAIT0; __syncthreads(); }
        if (more) { issueKV(kt + 1, st ^ 1); CP_COMMIT; }

        const uint32_t Kb = sb + (uint32_t)st * 4608u * 4u;
        const uint32_t Vb = sb + (9216u + (uint32_t)st * 4608u) * 4u;
        const bool dtile = (kt == qt);

#pragma unroll
        for (int hl = 0; hl < 2; hl++) {
            // ---- S = Qs @ K^T (64-key half), already in log2 domain ----
            float sacc[8][4];
#pragma unroll
            for (int a = 0; a < 8; a++)
#pragma unroll
                for (int c = 0; c < 4; c++) sacc[a][c] = 0.0f;
#pragma unroll
            for (int p = 0; p < 4; p++) {
                const uint32_t krow = (uint32_t)(hl * 64 + p * 16) + lrow8;
#pragma unroll
                for (int kk = 0; kk < 4; kk++) {
                    uint32_t kb[4];
                    ldm4(kb, Kb + krow * 144u + kk * 32u + lsel);
                    mma16(sacc[2 * p],     qf[kk], kb[0], kb[1]);
                    mma16(sacc[2 * p + 1], qf[kk], kb[2], kb[3]);
                }
            }
            // ---- P = 2^S via f16x2 MUFU (2 per op), mask on packed halves ----
            uint32_t pf01[8], pf23[8];
#pragma unroll
            for (int nt = 0; nt < 8; nt++) {
                uint32_t e01 = ex2h2(packh2(sacc[nt][0], sacc[nt][1]));
                uint32_t e23 = ex2h2(packh2(sacc[nt][2], sacc[nt][3]));
                if (dtile) {
                    int c0 = hl * 64 + nt * 8 + 2 * t4;
                    uint32_t m0 = (c0 <= r0l      ? 0x0000FFFFu : 0u) |
                                  (c0 + 1 <= r0l  ? 0xFFFF0000u : 0u);
                    uint32_t m1 = (c0 <= r0l + 8     ? 0x0000FFFFu : 0u) |
                                  (c0 + 1 <= r0l + 8 ? 0xFFFF0000u : 0u);
                    e01 &= m0; e23 &= m1;
                }
                pf01[nt] = e01; pf23[nt] = e23;
            }
            // ---- O += P @ V ; l += P @ ones (tensor-pipe row-sum) ----
#pragma unroll
            for (int kk = 0; kk < 4; kk++) {
                uint32_t af[4];
                af[0] = pf01[2 * kk];     af[1] = pf23[2 * kk];
                af[2] = pf01[2 * kk + 1]; af[3] = pf23[2 * kk + 1];
                mma16(lacc, af, ONESH2, ONESH2);
                const uint32_t vr = (uint32_t)(hl * 64 + kk * 16) + vrow;
#pragma unroll
                for (int p = 0; p < 4; p++) {
                    uint32_t vb[4];
                    ldm4t(vb, Vb + vr * 144u + (uint32_t)(p * 32) + vsel);
                    mma16(oacc[2 * p],     af, vb[0], vb[1]);
                    mma16(oacc[2 * p + 1], af, vb[2], vb[3]);
                }
            }
        }
    }

    // ---- epilogue: lacc[0]/lacc[2] hold complete row-sums in EVERY lane ----
    if (ns == 1) {
        const float inv0 = 1.0f / lacc[0];
        const float inv1 = 1.0f / lacc[2];
        float* og = outp + ((size_t)b * SEQ + qBase + r0l) * HDIM;
#pragma unroll
        for (int nt = 0; nt < 8; nt++) {
            int cc = nt * 8 + 2 * t4;
            float2 v0 = { oacc[nt][0] * inv0, oacc[nt][1] * inv0 };
            *reinterpret_cast<float2*>(og + cc) = v0;
            float2 v1 = { oacc[nt][2] * inv1, oacc[nt][3] * inv1 };
            *reinterpret_cast<float2*>(og + (size_t)8 * HDIM + cc) = v1;
        }
    } else {
        float* po = g_partO[s] + ((size_t)b * SEQ + qBase + r0l) * HDIM;
#pragma unroll
        for (int nt = 0; nt < 8; nt++) {
            int cc = nt * 8 + 2 * t4;
            float2 v0 = { oacc[nt][0], oacc[nt][1] };
            *reinterpret_cast<float2*>(po + cc) = v0;
            float2 v1 = { oacc[nt][2], oacc[nt][3] };
            *reinterpret_cast<float2*>(po + (size_t)8 * HDIM + cc) = v1;
        }
        if (t4 == 0) {
            g_partL[s][(size_t)b * SEQ + qBase + r0l]     = lacc[0];
            g_partL[s][(size_t)b * SEQ + qBase + r0l + 8] = lacc[2];
        }
    }
}

// ================= Kernel 3: combine splits (rows with qt >= 4 only) =================
// 8 batches x 1536 rows x 16 float4, 2 float4/thread -> 384 blocks.
__global__ void __launch_bounds__(256) combine_kernel(float* __restrict__ out)
{
    int base2 = (blockIdx.x * 256 + threadIdx.x) * 2;
    int bb  = base2 / 24576;                 // 1536 rows * 16 f4 per batch
    int rem = base2 - bb * 24576;
    int rowInB = 512 + (rem >> 4);
    int row = bb * SEQ + rowInB;
    int f4i = row * 16 + (rem & 15);
    int qt = rowInB >> 7;
    int ns = (qt + 4) / 4;                   // >= 2 here

    float4 o0 = reinterpret_cast<const float4*>(g_partO[0])[f4i];
    float4 o1 = reinterpret_cast<const float4*>(g_partO[0])[f4i + 1];
    float4 a0 = reinterpret_cast<const float4*>(g_partO[1])[f4i];
    float4 a1 = reinterpret_cast<const float4*>(g_partO[1])[f4i + 1];
    float  l  = g_partL[0][row] + g_partL[1][row];
    o0.x += a0.x; o0.y += a0.y; o0.z += a0.z; o0.w += a0.w;
    o1.x += a1.x; o1.y += a1.y; o1.z += a1.z; o1.w += a1.w;
#pragma unroll
    for (int s = 2; s < 4; s++) {
        if (ns > s) {
            float4 c0 = reinterpret_cast<const float4*>(g_partO[s])[f4i];
            float4 c1 = reinterpret_cast<const float4*>(g_partO[s])[f4i + 1];
            o0.x += c0.x; o0.y += c0.y; o0.z += c0.z; o0.w += c0.w;
            o1.x += c1.x; o1.y += c1.y; o1.z += c1.z; o1.w += c1.w;
            l += g_partL[s][row];
        }
    }
    float inv = 1.0f / l;
    o0.x *= inv; o0.y *= inv; o0.z *= inv; o0.w *= inv;
    o1.x *= inv; o1.y *= inv; o1.z *= inv; o1.w *= inv;
    reinterpret_cast<float4*>(out)[f4i]     = o0;
    reinterpret_cast<float4*>(out)[f4i + 1] = o1;
}

// ---------------- launch ----------------
extern "C" void kernel_launch(void* const* d_in, const int* in_sizes, int n_in,
                              void* d_out, int out_size)
{
    const float* x  = (const float*)d_in[0];
    const float* Wq = (const float*)d_in[1];
    const float* Wk = (const float*)d_in[2];
    const float* Wv = (const float*)d_in[3];
    float* out = (float*)d_out;

    wt_kernel<<<dim3(CDIM / 32, HDIM / 32, 3), dim3(32, 32)>>>(Wq, Wk, Wv);

    cudaFuncSetAttribute(qkv_mma, cudaFuncAttributeMaxDynamicSharedMemorySize,
                         QKV_SMEM_BYTES);
    qkv_mma<<<(BATCH * SEQ) / 128, 512, QKV_SMEM_BYTES>>>(x);

    cudaFuncSetAttribute(attn_split, cudaFuncAttributeMaxDynamicSharedMemorySize,
                         ATTN_SMEM_BYTES);
    attn_split<<<320, 256, ATTN_SMEM_BYTES>>>(out);

    // rows with qt<4 were written directly by attn_split (ns==1)
    combine_kernel<<<(BATCH * 1536 * 16 / 2) / 256, 256>>>(out);
}

// round 14
// speedup vs baseline: 2.0401x; 1.0898x over previous
#include <cuda_runtime.h>
#include <cuda_fp16.h>
#include <cstdint>

#define BATCH 8
#define SEQ   2048
#define CDIM  1024
#define HDIM  64

// ---------------- persistent scratch ----------------
__device__ __half g_wth[3 * HDIM * CDIM];          // [192 n][1024 k] fp16 W^T
__device__ __half g_qh[BATCH * SEQ * HDIM];        // q PRE-SCALED by 0.125*log2(e)
__device__ __half g_kh[BATCH * SEQ * HDIM];
__device__ __half g_vh[BATCH * SEQ * HDIM];
__device__ float  g_partO[4][BATCH * SEQ * HDIM];
__device__ float  g_partL[4][BATCH * SEQ];

#define QSCALE 0.18033688011112042f   /* 0.125 * log2(e) */
#define ONESH2 0x3C003C00u            /* {1.0h, 1.0h}     */

// ---------------- helpers ----------------
__device__ __forceinline__ uint32_t smem_u32(const void* p) {
    uint32_t a;
    asm("{ .reg .u64 t; cvta.to.shared.u64 t, %1; cvt.u32.u64 %0, t; }" : "=r"(a) : "l"(p));
    return a;
}
__device__ __forceinline__ void cp16(uint32_t dst, const void* src) {
    asm volatile("cp.async.cg.shared.global [%0], [%1], 16;" :: "r"(dst), "l"(src));
}
#define CP_COMMIT asm volatile("cp.async.commit_group;" ::: "memory")
#define CP_WAIT0  asm volatile("cp.async.wait_group 0;" ::: "memory")

__device__ __forceinline__ uint32_t packh2(float lo, float hi) {
    uint32_t d;
    asm("cvt.rn.f16x2.f32 %0, %1, %2;" : "=r"(d) : "f"(hi), "f"(lo));
    return d;
}
__device__ __forceinline__ uint32_t ex2h2(uint32_t x) {
    uint32_t d;
    asm("ex2.approx.f16x2 %0, %1;" : "=r"(d) : "r"(x));
    return d;
}
__device__ __forceinline__ void mma16(float* c, const uint32_t* a, uint32_t b0, uint32_t b1) {
    asm volatile(
        "mma.sync.aligned.m16n8k16.row.col.f32.f16.f16.f32 "
        "{%0,%1,%2,%3}, {%4,%5,%6,%7}, {%8,%9}, {%0,%1,%2,%3};"
        : "+f"(c[0]), "+f"(c[1]), "+f"(c[2]), "+f"(c[3])
        : "r"(a[0]), "r"(a[1]), "r"(a[2]), "r"(a[3]), "r"(b0), "r"(b1));
}
__device__ __forceinline__ void ldm4(uint32_t* r, uint32_t addr) {
    asm volatile("ldmatrix.sync.aligned.m8n8.x4.shared.b16 {%0,%1,%2,%3}, [%4];"
                 : "=r"(r[0]), "=r"(r[1]), "=r"(r[2]), "=r"(r[3]) : "r"(addr));
}
__device__ __forceinline__ void ldm4t(uint32_t* r, uint32_t addr) {
    asm volatile("ldmatrix.sync.aligned.m8n8.x4.trans.shared.b16 {%0,%1,%2,%3}, [%4];"
                 : "=r"(r[0]), "=r"(r[1]), "=r"(r[2]), "=r"(r[3]) : "r"(addr));
}

// ================= Kernel 0: W transpose + fp16 =================
__global__ void wt_kernel(const float* __restrict__ Wq,
                          const float* __restrict__ Wk,
                          const float* __restrict__ Wv)
{
    const float* W = (blockIdx.z == 0) ? Wq : (blockIdx.z == 1) ? Wk : Wv;
    __shared__ float tile[32][33];
    int c0 = blockIdx.x * 32, h0 = blockIdx.y * 32;
    tile[threadIdx.y][threadIdx.x] = W[(size_t)(c0 + threadIdx.y) * HDIM + h0 + threadIdx.x];
    __syncthreads();
    g_wth[(size_t)blockIdx.z * HDIM * CDIM + (size_t)(h0 + threadIdx.y) * CDIM + c0 + threadIdx.x] =
        __float2half_rn(tile[threadIdx.x][threadIdx.y]);
}

// ================= Kernel 1: fused QKV projection =================
// grid 256 x 256 thr, 2 CTAs/SM -> one 296-slot wave, all SMs busy.
// 64-row M-tile, K-chunk 64 (4 k16 steps), double-buffered, 1 sync/iter.
// SMEM words: A0[64*36]@0  A1@2304  B0[192*36]@4608  B1@11520  -> 73728 B
#define QKV_SMEM_BYTES 73728

__global__ void __launch_bounds__(256, 2) qkv_mma(const float* __restrict__ x)
{
    extern __shared__ uint32_t smw[];
    const uint32_t sb = smem_u32(smw);
    const int t = threadIdx.x, lane = t & 31, warp = t >> 5;
    const int g = lane >> 2, t4 = lane & 3;
    const int wm = warp >> 2, wn = warp & 3;           // 2M x 4N warps
    const int Mbase = blockIdx.x * 64;

    const uint32_t arow = lane & 15;
    const uint32_t asel = (uint32_t)((lane >> 4) << 4);
    const uint32_t nrow = (uint32_t)(((lane >> 4) << 3) + (lane & 7));
    const uint32_t bsel = (uint32_t)(((lane >> 3) & 1) << 4);

    float acc[2][6][4];
#pragma unroll
    for (int a = 0; a < 2; a++)
#pragma unroll
        for (int b = 0; b < 6; b++)
#pragma unroll
            for (int c = 0; c < 4; c++) acc[a][b][c] = 0.0f;

    const int xr = t >> 2, xj = t & 3;

    auto ldgX = [&](int c, float4* v) {
        const float* src = x + (size_t)(Mbase + xr) * CDIM + c * 64 + xj * 16;
#pragma unroll
        for (int i = 0; i < 4; i++) v[i] = *reinterpret_cast<const float4*>(src + i * 4);
    };
    auto stsX = [&](int st, const float4* v) {
        uint4 h0, h1;
        h0.x = packh2(v[0].x, v[0].y); h0.y = packh2(v[0].z, v[0].w);
        h0.z = packh2(v[1].x, v[1].y); h0.w = packh2(v[1].z, v[1].w);
        h1.x = packh2(v[2].x, v[2].y); h1.y = packh2(v[2].z, v[2].w);
        h1.z = packh2(v[3].x, v[3].y); h1.w = packh2(v[3].z, v[3].w);
        *reinterpret_cast<uint4*>(smw + st * 2304 + xr * 36 + xj * 8)     = h0;
        *reinterpret_cast<uint4*>(smw + st * 2304 + xr * 36 + xj * 8 + 4) = h1;
    };
    auto issueB = [&](int c, int st) {
        uint32_t bb = sb + (4608u + (uint32_t)st * 6912u) * 4u;
#pragma unroll
        for (int i = 0; i < 6; i++) {
            int idx = t + i * 256;
            int n = idx >> 3, j = idx & 7;
            cp16(bb + (uint32_t)(n * 36 + j * 4) * 4u,
                 g_wth + (size_t)n * CDIM + c * 64 + j * 8);
        }
    };

    float4 xa[4];
    ldgX(0, xa); stsX(0, xa);
    issueB(0, 0); CP_COMMIT;

    for (int c = 0; c < 16; c++) {
        const int st = c & 1;
        CP_WAIT0;
        __syncthreads();
        if (c < 15) { issueB(c + 1, st ^ 1); CP_COMMIT; ldgX(c + 1, xa); }

        const uint32_t Ab = sb + (uint32_t)st * 2304u * 4u;
        const uint32_t Bb = sb + (4608u + (uint32_t)st * 6912u) * 4u;

#pragma unroll
        for (int kk = 0; kk < 4; kk++) {
            uint32_t af0[4], af1[4];
            ldm4(af0, Ab + (wm * 32 +      arow) * 144u + kk * 32u + asel);
            ldm4(af1, Ab + (wm * 32 + 16 + arow) * 144u + kk * 32u + asel);
#pragma unroll
            for (int j = 0; j < 3; j++) {
                uint32_t bf[4];
                ldm4(bf, Bb + (wn * 48 + j * 16 + nrow) * 144u + kk * 32u + bsel);
                mma16(acc[0][2 * j],     af0, bf[0], bf[1]);
                mma16(acc[0][2 * j + 1], af0, bf[2], bf[3]);
                mma16(acc[1][2 * j],     af1, bf[0], bf[1]);
                mma16(acc[1][2 * j + 1], af1, bf[2], bf[3]);
            }
        }
        if (c < 15) stsX(st ^ 1, xa);
    }

    // epilogue: q is pre-scaled by QSCALE (softmax scale folded into log2 domain)
#pragma unroll
    for (int mt = 0; mt < 2; mt++) {
        int r0 = Mbase + wm * 32 + mt * 16 + g;
#pragma unroll
        for (int nt = 0; nt < 6; nt++) {
            int ncol = wn * 48 + nt * 8 + 2 * t4;
            int w = ncol >> 6, cc = ncol & 63;
            __half* outp = (w == 0) ? g_qh : (w == 1) ? g_kh : g_vh;
            float sc = (w == 0) ? QSCALE : 1.0f;
            *reinterpret_cast<uint32_t*>(outp + (size_t)r0 * HDIM + cc) =
                packh2(acc[mt][nt][0] * sc, acc[mt][nt][1] * sc);
            *reinterpret_cast<uint32_t*>(outp + (size_t)(r0 + 8) * HDIM + cc) =
                packh2(acc[mt][nt][2] * sc, acc[mt][nt][3] * sc);
        }
    }
}

// ================= Kernel 2: split-K causal attention =================
// 272 CTAs (34/batch), max 5 key-tile iters -> ONE wave at 2 CTAs/SM.
// ns(qt)=ceil((qt+1)/5). ns==1 (qt<=4) writes normalized output directly.
// Diagonal tiles: warps 0-3 skip the fully-masked hl=1 half.
// SMEM words: K0@0 K1@4608 V0@9216 V1@13824 Q@18432 (each 4608) -> 92160 B
#define ATTN_SMEM_BYTES 92160

__global__ void __launch_bounds__(256, 2) attn_split(float* __restrict__ outp)
{
    extern __shared__ uint32_t smw[];
    const uint32_t sb = smem_u32(smw);
    const int t = threadIdx.x, lane = t & 31, warp = t >> 5;
    const int g = lane >> 2, t4 = lane & 3;

    const int bid = blockIdx.x;
    const int b = bid / 34, r = bid % 34;
    int qt, s, ns;
    if (r < 5)        { qt = r;                 s = 0;            ns = 1; }
    else if (r < 15)  { qt = 5 + (r - 5) / 2;   s = (r - 5) % 2;  ns = 2; }
    else if (r < 30)  { qt = 10 + (r - 15) / 3; s = (r - 15) % 3; ns = 3; }
    else              { qt = 15;                s = r - 30;       ns = 4; }
    const int len = qt + 1;
    const int k0t = s * len / ns, k1t = (s + 1) * len / ns;
    const int qBase = qt * 128;

    const __half* kg = g_kh + (size_t)b * SEQ * HDIM;
    const __half* vg = g_vh + (size_t)b * SEQ * HDIM;

    const uint32_t lrow8 = (uint32_t)(((lane >> 4) << 3) + (lane & 7));
    const uint32_t lsel  = (uint32_t)(((lane >> 3) & 1) << 4);
    const uint32_t vrow  = (uint32_t)((((lane >> 3) & 1) << 3) + (lane & 7));
    const uint32_t vsel  = (uint32_t)((lane >> 4) << 4);

    auto issueKV = [&](int kt, int st) {
        uint32_t kb = sb + (uint32_t)st * 4608u * 4u;
        uint32_t vb = sb + (9216u + (uint32_t)st * 4608u) * 4u;
#pragma unroll
        for (int i = 0; i < 4; i++) {
            int idx = t + i * 256;
            int rr = idx >> 3, j = idx & 7;
            cp16(kb + (uint32_t)(rr * 36 + j * 4) * 4u,
                 kg + (size_t)(kt * 128 + rr) * HDIM + j * 8);
            cp16(vb + (uint32_t)(rr * 36 + j * 4) * 4u,
                 vg + (size_t)(kt * 128 + rr) * HDIM + j * 8);
        }
    };

    issueKV(k0t, 0);
    {
        const __half* qg = g_qh + ((size_t)b * SEQ + qBase) * HDIM;
#pragma unroll
        for (int i = 0; i < 4; i++) {
            int idx = t + i * 256;
            int rr = idx >> 3, j = idx & 7;
            cp16(sb + (uint32_t)(18432 + rr * 36 + j * 4) * 4u,
                 qg + (size_t)rr * HDIM + j * 8);
        }
    }
    CP_COMMIT;
    CP_WAIT0;
    __syncthreads();

    uint32_t qf[4][4];
    {
        const uint32_t Qb = sb + 18432u * 4u;
        const uint32_t qrow = (uint32_t)(warp * 16 + (lane & 15));
        const uint32_t qsel = (uint32_t)((lane >> 4) << 4);
#pragma unroll
        for (int kk = 0; kk < 4; kk++) ldm4(qf[kk], Qb + qrow * 144u + kk * 32u + qsel);
    }

    float oacc[8][4];
#pragma unroll
    for (int a = 0; a < 8; a++)
#pragma unroll
        for (int c = 0; c < 4; c++) oacc[a][c] = 0.0f;
    float lacc[4] = {0.0f, 0.0f, 0.0f, 0.0f};
    const int r0l = warp * 16 + g;

    for (int kt = k0t; kt < k1t; kt++) {
        const int st = (kt - k0t) & 1;
        const bool more = (kt + 1 < k1t);
        if (kt > k0t) { CP_WAIT0; __syncthreads(); }
        if (more) { issueKV(kt + 1, st ^ 1); CP_COMMIT; }

        const uint32_t Kb = sb + (uint32_t)st * 4608u * 4u;
        const uint32_t Vb = sb + (9216u + (uint32_t)st * 4608u) * 4u;
        const bool dtile = (kt == qt);

#pragma unroll
        for (int hl = 0; hl < 2; hl++) {
            // diagonal tile: warps 0-3 (queries 0-63) see only masked keys in hl=1
            if (dtile && hl == 1 && warp < 4) continue;

            // ---- S = Qs @ K^T (64-key half), already in log2 domain ----
            float sacc[8][4];
#pragma unroll
            for (int a = 0; a < 8; a++)
#pragma unroll
                for (int c = 0; c < 4; c++) sacc[a][c] = 0.0f;
#pragma unroll
            for (int p = 0; p < 4; p++) {
                const uint32_t krow = (uint32_t)(hl * 64 + p * 16) + lrow8;
#pragma unroll
                for (int kk = 0; kk < 4; kk++) {
                    uint32_t kb[4];
                    ldm4(kb, Kb + krow * 144u + kk * 32u + lsel);
                    mma16(sacc[2 * p],     qf[kk], kb[0], kb[1]);
                    mma16(sacc[2 * p + 1], qf[kk], kb[2], kb[3]);
                }
            }
            // ---- P = 2^S via f16x2 MUFU, mask on packed halves ----
            uint32_t pf01[8], pf23[8];
#pragma unroll
            for (int nt = 0; nt < 8; nt++) {
                uint32_t e01 = ex2h2(packh2(sacc[nt][0], sacc[nt][1]));
                uint32_t e23 = ex2h2(packh2(sacc[nt][2], sacc[nt][3]));
                if (dtile) {
                    int c0 = hl * 64 + nt * 8 + 2 * t4;
                    uint32_t m0 = (c0 <= r0l      ? 0x0000FFFFu : 0u) |
                                  (c0 + 1 <= r0l  ? 0xFFFF0000u : 0u);
                    uint32_t m1 = (c0 <= r0l + 8     ? 0x0000FFFFu : 0u) |
                                  (c0 + 1 <= r0l + 8 ? 0xFFFF0000u : 0u);
                    e01 &= m0; e23 &= m1;
                }
                pf01[nt] = e01; pf23[nt] = e23;
            }
            // ---- O += P @ V ; l += P @ ones (tensor-pipe row-sum) ----
#pragma unroll
            for (int kk = 0; kk < 4; kk++) {
                uint32_t af[4];
                af[0] = pf01[2 * kk];     af[1] = pf23[2 * kk];
                af[2] = pf01[2 * kk + 1]; af[3] = pf23[2 * kk + 1];
                mma16(lacc, af, ONESH2, ONESH2);
                const uint32_t vr = (uint32_t)(hl * 64 + kk * 16) + vrow;
#pragma unroll
                for (int p = 0; p < 4; p++) {
                    uint32_t vb[4];
                    ldm4t(vb, Vb + vr * 144u + (uint32_t)(p * 32) + vsel);
                    mma16(oacc[2 * p],     af, vb[0], vb[1]);
                    mma16(oacc[2 * p + 1], af, vb[2], vb[3]);
                }
            }
        }
    }

    // ---- epilogue: lacc[0]/lacc[2] hold complete row-sums in EVERY lane ----
    if (ns == 1) {
        const float inv0 = 1.0f / lacc[0];
        const float inv1 = 1.0f / lacc[2];
        float* og = outp + ((size_t)b * SEQ + qBase + r0l) * HDIM;
#pragma unroll
        for (int nt = 0; nt < 8; nt++) {
            int cc = nt * 8 + 2 * t4;
            float2 v0 = { oacc[nt][0] * inv0, oacc[nt][1] * inv0 };
            *reinterpret_cast<float2*>(og + cc) = v0;
            float2 v1 = { oacc[nt][2] * inv1, oacc[nt][3] * inv1 };
            *reinterpret_cast<float2*>(og + (size_t)8 * HDIM + cc) = v1;
        }
    } else {
        float* po = g_partO[s] + ((size_t)b * SEQ + qBase + r0l) * HDIM;
#pragma unroll
        for (int nt = 0; nt < 8; nt++) {
            int cc = nt * 8 + 2 * t4;
            float2 v0 = { oacc[nt][0], oacc[nt][1] };
            *reinterpret_cast<float2*>(po + cc) = v0;
            float2 v1 = { oacc[nt][2], oacc[nt][3] };
            *reinterpret_cast<float2*>(po + (size_t)8 * HDIM + cc) = v1;
        }
        if (t4 == 0) {
            g_partL[s][(size_t)b * SEQ + qBase + r0l]     = lacc[0];
            g_partL[s][(size_t)b * SEQ + qBase + r0l + 8] = lacc[2];
        }
    }
}

// ================= Kernel 3: combine splits (rows with qt >= 5 only) =================
// 8 batches x 1408 rows x 16 float4, 2 float4/thread -> 352 blocks.
__global__ void __launch_bounds__(256) combine_kernel(float* __restrict__ out)
{
    int base2 = (blockIdx.x * 256 + threadIdx.x) * 2;
    int bb  = base2 / 22528;                 // 1408 rows * 16 f4 per batch
    int rem = base2 - bb * 22528;
    int rowInB = 640 + (rem >> 4);
    int row = bb * SEQ + rowInB;
    int f4i = row * 16 + (rem & 15);
    int qt = rowInB >> 7;
    int ns = (qt + 5) / 5;                   // 2..4 here

    float4 o0 = reinterpret_cast<const float4*>(g_partO[0])[f4i];
    float4 o1 = reinterpret_cast<const float4*>(g_partO[0])[f4i + 1];
    float4 a0 = reinterpret_cast<const float4*>(g_partO[1])[f4i];
    float4 a1 = reinterpret_cast<const float4*>(g_partO[1])[f4i + 1];
    float  l  = g_partL[0][row] + g_partL[1][row];
    o0.x += a0.x; o0.y += a0.y; o0.z += a0.z; o0.w += a0.w;
    o1.x += a1.x; o1.y += a1.y; o1.z += a1.z; o1.w += a1.w;
#pragma unroll
    for (int s = 2; s < 4; s++) {
        if (ns > s) {
            float4 c0 = reinterpret_cast<const float4*>(g_partO[s])[f4i];
            float4 c1 = reinterpret_cast<const float4*>(g_partO[s])[f4i + 1];
            o0.x += c0.x; o0.y += c0.y; o0.z += c0.z; o0.w += c0.w;
            o1.x += c1.x; o1.y += c1.y; o1.z += c1.z; o1.w += c1.w;
            l += g_partL[s][row];
        }
    }
    float inv = 1.0f / l;
    o0.x *= inv; o0.y *= inv; o0.z *= inv; o0.w *= inv;
    o1.x *= inv; o1.y *= inv; o1.z *= inv; o1.w *= inv;
    reinterpret_cast<float4*>(out)[f4i]     = o0;
    reinterpret_cast<float4*>(out)[f4i + 1] = o1;
}

// ---------------- launch ----------------
extern "C" void kernel_launch(void* const* d_in, const int* in_sizes, int n_in,
                              void* d_out, int out_size)
{
    const float* x  = (const float*)d_in[0];
    const float* Wq = (const float*)d_in[1];
    const float* Wk = (const float*)d_in[2];
    const float* Wv = (const float*)d_in[3];
    float* out = (float*)d_out;

    wt_kernel<<<dim3(CDIM / 32, HDIM / 32, 3), dim3(32, 32)>>>(Wq, Wk, Wv);

    cudaFuncSetAttribute(qkv_mma, cudaFuncAttributeMaxDynamicSharedMemorySize,
                         QKV_SMEM_BYTES);
    qkv_mma<<<(BATCH * SEQ) / 64, 256, QKV_SMEM_BYTES>>>(x);

    cudaFuncSetAttribute(attn_split, cudaFuncAttributeMaxDynamicSharedMemorySize,
                         ATTN_SMEM_BYTES);
    attn_split<<<272, 256, ATTN_SMEM_BYTES>>>(out);

    // rows with qt<5 were written directly by attn_split (ns==1)
    combine_kernel<<<352, 256>>>(out);
}